// round 10
// baseline (speedup 1.0000x reference)
#include <cuda_runtime.h>
#include <cuda_fp16.h>

#define NN 50000
#define NP 800000   // undirected pairs
#define NE 1600000  // directed edges

// ---------------- scratch (static device globals; no allocations) ----------------
__device__ float  g_x1[NN * 64];
__device__ float  g_x2[NN * 64];
__device__ int    g_cnt[NN];
__device__ int    g_offs[NN + 1];
__device__ int    g_cur[NN];
__device__ int    g_srcs[NE];
__device__ __half g_PA[NN * 256];     // fp16 projection table A (conv1/conv2/ec2)
__device__ __half g_PB[NN * 256];     // fp16 projection table B (ec1)
__device__ float  g_Wc[16384];        // ec1: W1 @ Wl[0:128]
__device__ float  g_c0[128];          // ec1: b1 @ Wl[0:128] + bl
__device__ float  g_Wc2[384];         // ec2: 0.5 * W1e2 @ Wl2[0:3]
__device__ float  g_c2[4];            // ec2: b1e2 @ Wl2[0:3] + bl2
__device__ float  g_Wcc[384];         // 0.5 * Wc @ WlB   (fe1 folded into ec2)
__device__ float  g_wa3[4];           // wl128 @ WlB
__device__ float  g_wg3[4];           // wl129 @ WlB
__device__ float  g_cc[4];            // c0 @ WlB + c2
__device__ double g_loss[2];

__device__ __forceinline__ float lrelu(float z) { return z > 0.f ? z : 0.01f * z; }

__device__ __forceinline__ unsigned tf32_bits(float x)
{
    unsigned r;
    asm("cvt.rna.tf32.f32 %0, %1;" : "=r"(r) : "f"(x));
    return r;
}

__device__ __forceinline__ void mma_tf32(float c[4],
    unsigned a0, unsigned a1, unsigned a2, unsigned a3,
    unsigned b0, unsigned b1)
{
    asm volatile(
        "mma.sync.aligned.m16n8k8.row.col.f32.tf32.tf32.f32 "
        "{%0,%1,%2,%3}, {%4,%5,%6,%7}, {%8,%9}, {%0,%1,%2,%3};"
        : "+f"(c[0]), "+f"(c[1]), "+f"(c[2]), "+f"(c[3])
        : "r"(a0), "r"(a1), "r"(a2), "r"(a3), "r"(b0), "r"(b1));
}

// ---------------- packed f32x2 helpers ----------------
__device__ __forceinline__ unsigned long long pack2(float x)
{
    unsigned long long r;
    asm("mov.b64 %0, {%1, %1};" : "=l"(r) : "f"(x));
    return r;
}
__device__ __forceinline__ unsigned long long ffma2(
    unsigned long long a, unsigned long long b, unsigned long long c)
{
    unsigned long long d;
    asm("fma.rn.f32x2 %0, %1, %2, %3;" : "=l"(d) : "l"(a), "l"(b), "l"(c));
    return d;
}
__device__ __forceinline__ void unpack2(unsigned long long v, float& lo, float& hi)
{
    asm("mov.b64 {%0, %1}, %2;" : "=f"(lo), "=f"(hi) : "l"(v));
}

// half4 (uint2) -> 4 floats
__device__ __forceinline__ void h4_to_f4(uint2 u, float& f0, float& f1, float& f2, float& f3)
{
    __half2 p01 = *(__half2*)&u.x;
    __half2 p23 = *(__half2*)&u.y;
    float2 a = __half22float2(p01);
    float2 b = __half22float2(p23);
    f0 = a.x; f1 = a.y; f2 = b.x; f3 = b.y;
}

// ------------------------------------------------------------------
// Weight fusion precompute kernels (run once per call, tiny)
__global__ void fuseA_kernel(const float* __restrict__ W1, const float* __restrict__ Wl,
                             float* __restrict__ Wc)
{
    int id = blockIdx.x * 256 + threadIdx.x;   // 16384
    int r = id >> 7, c = id & 127;
    float s = 0.f;
#pragma unroll 8
    for (int k = 0; k < 128; k++) s += W1[r * 128 + k] * Wl[k * 128 + c];
    Wc[id] = s;
}
__global__ void fuseA2_kernel(const float* __restrict__ Wl, const float* __restrict__ b1,
                              const float* __restrict__ bl, float* __restrict__ c0)
{
    int c = threadIdx.x;   // 128
    float s = bl[c];
#pragma unroll 8
    for (int k = 0; k < 128; k++) s += b1[k] * Wl[k * 128 + c];
    c0[c] = s;
}
__global__ void fuseB_kernel(const float* __restrict__ W1e, const float* __restrict__ Wl2,
                             const float* __restrict__ b1, const float* __restrict__ bl,
                             float* __restrict__ Wc2, float* __restrict__ c2)
{
    int id = threadIdx.x;   // 384
    if (id < 384) {
        int k = id / 3, c = id % 3;
        Wc2[id] = 0.5f * (W1e[k * 3 + 0] * Wl2[0 + c] +
                          W1e[k * 3 + 1] * Wl2[3 + c] +
                          W1e[k * 3 + 2] * Wl2[6 + c]);
    }
    if (id < 3)
        c2[id] = b1[0] * Wl2[0 + id] + b1[1] * Wl2[3 + id] + b1[2] * Wl2[6 + id] + bl[id];
}
// Wcc = 0.5 * Wc @ WlB ; wa3/wg3 = Wl rows 128/129 @ WlB ; cc = c0 @ WlB + c2
__global__ void fuseC_kernel(const float* __restrict__ Wc, const float* __restrict__ c0,
                             const float* __restrict__ Wl1, const float* __restrict__ Wl2,
                             const float* __restrict__ c2,
                             float* __restrict__ Wcc, float* __restrict__ wa3,
                             float* __restrict__ wg3, float* __restrict__ cc)
{
    int id = threadIdx.x;   // 384
    int k = id / 3, c = id % 3;
    float s = 0.f;
#pragma unroll 8
    for (int j = 0; j < 128; j++) s += Wc[k * 128 + j] * Wl2[(3 + j) * 3 + c];
    Wcc[id] = 0.5f * s;
    if (id < 3) {
        float sa = 0.f, sg = 0.f, sc = 0.f;
        for (int j = 0; j < 128; j++) {
            float wb = Wl2[(3 + j) * 3 + id];
            sa += Wl1[128 * 128 + j] * wb;
            sg += Wl1[129 * 128 + j] * wb;
            sc += c0[j] * wb;
        }
        wa3[id] = sa; wg3[id] = sg; cc[id] = sc + c2[id];
    }
}

// ------------------------------------------------------------------
// CSR build: count (dst degrees) -> scan -> fill
__global__ void count_kernel(const int* __restrict__ ei, int* __restrict__ cnt)
{
    int e = blockIdx.x * blockDim.x + threadIdx.x;
    if (e < NE) atomicAdd(&cnt[ei[NE + e]], 1);
}

__global__ void __launch_bounds__(1024) scan_kernel(const int* __restrict__ cnt,
                                                    int* __restrict__ offs)
{
    __shared__ int part[1024];
    const int t = threadIdx.x;
    const int CH = (NN + 1023) / 1024;   // 49
    const int base = t * CH;
    int s = 0;
    for (int j = 0; j < CH; j++) {
        int n = base + j;
        if (n < NN) s += cnt[n];
    }
    part[t] = s;
    __syncthreads();
    for (int off = 1; off < 1024; off <<= 1) {
        int v = (t >= off) ? part[t - off] : 0;
        __syncthreads();
        part[t] += v;
        __syncthreads();
    }
    int run = part[t] - s;
    for (int j = 0; j < CH; j++) {
        int n = base + j;
        if (n < NN) { offs[n] = run; run += cnt[n]; }
    }
    if (t == 1023) offs[NN] = part[1023];
}

__global__ void fill_kernel(const int* __restrict__ ei, const int* __restrict__ offs,
                            int* __restrict__ cur, int* __restrict__ srcs)
{
    int e = blockIdx.x * blockDim.x + threadIdx.x;
    if (e < NE) {
        int src = ei[e];
        int dst = ei[NE + e];
        int pos = atomicAdd(&cur[dst], 1);
        srcs[offs[dst] + pos] = src;
    }
}

// ------------------------------------------------------------------
// node_proj: P[n][0..127] = x[n] @ W0[0:64,:] ; P[n][128..255] = x[n] @ W0[64:128,:]
// fp16 output (all consumers gather fp16)
__global__ void __launch_bounds__(256) node_proj_kernel(
    const float* __restrict__ x, const float* __restrict__ W0, __half* __restrict__ Ph)
{
    __shared__ float XT[64 * 68];
    __shared__ float WC[16 * 256];
    const int tid = threadIdx.x;
    const int nbase = blockIdx.x * 64;
#pragma unroll
    for (int i = 0; i < 4; i++) {
        int lin = tid * 4 + i;
        int r = lin >> 4, q = lin & 15;
        int node = nbase + r; if (node >= NN) node = NN - 1;
        float4 v = __ldg((const float4*)x + (size_t)node * 16 + q);
        XT[(q * 4 + 0) * 68 + r] = v.x;
        XT[(q * 4 + 1) * 68 + r] = v.y;
        XT[(q * 4 + 2) * 68 + r] = v.z;
        XT[(q * 4 + 3) * 68 + r] = v.w;
    }
    unsigned long long acc2[8][4];
#pragma unroll
    for (int i = 0; i < 8; i++)
#pragma unroll
        for (int j = 0; j < 4; j++) acc2[i][j] = 0ull;
    const int tr = tid >> 5, tc = tid & 31;
    for (int kc = 0; kc < 64; kc += 16) {
        __syncthreads();
#pragma unroll
        for (int i = 0; i < 4; i++) {
            int lin = tid + i * 256;
            int kk = lin >> 6, j4 = lin & 63;
            int j = j4 * 4;
            const float* src = (j < 128) ? (W0 + (kc + kk) * 128 + j)
                                         : (W0 + (64 + kc + kk) * 128 + (j - 128));
            *(float4*)&WC[kk * 256 + j] = *(const float4*)src;
        }
        __syncthreads();
#pragma unroll
        for (int kk = 0; kk < 16; kk++) {
            float4 a0 = *(const float4*)&XT[(kc + kk) * 68 + tr * 8];
            float4 a1 = *(const float4*)&XT[(kc + kk) * 68 + tr * 8 + 4];
            ulonglong2 w01 = *(const ulonglong2*)&WC[kk * 256 + tc * 8];
            ulonglong2 w23 = *(const ulonglong2*)&WC[kk * 256 + tc * 8 + 4];
            float a[8] = {a0.x, a0.y, a0.z, a0.w, a1.x, a1.y, a1.z, a1.w};
#pragma unroll
            for (int i = 0; i < 8; i++) {
                unsigned long long ap = pack2(a[i]);
                acc2[i][0] = ffma2(ap, w01.x, acc2[i][0]);
                acc2[i][1] = ffma2(ap, w01.y, acc2[i][1]);
                acc2[i][2] = ffma2(ap, w23.x, acc2[i][2]);
                acc2[i][3] = ffma2(ap, w23.y, acc2[i][3]);
            }
        }
    }
#pragma unroll
    for (int i = 0; i < 8; i++) {
        int node = nbase + tr * 8 + i;
        if (node < NN) {
            float o[8];
#pragma unroll
            for (int j = 0; j < 4; j++) unpack2(acc2[i][j], o[2 * j], o[2 * j + 1]);
            __half2 h0 = __floats2half2_rn(o[0], o[1]);
            __half2 h1 = __floats2half2_rn(o[2], o[3]);
            __half2 h2 = __floats2half2_rn(o[4], o[5]);
            __half2 h3 = __floats2half2_rn(o[6], o[7]);
            uint4 v;
            v.x = *(unsigned*)&h0; v.y = *(unsigned*)&h1;
            v.z = *(unsigned*)&h2; v.w = *(unsigned*)&h3;
            *(uint4*)&Ph[(size_t)node * 256 + tc * 8] = v;
        }
    }
}

// ------------------------------------------------------------------
// Fused CSR aggregation + per-node GEMM:
//   h[n] = sum over in-edges (src->n) of lrelu(Pt[src]+Pb[n]+b0)   (fp16 gathers)
//   x[n] = (h @ W1) / max(deg,1) + b1*(deg>0)
// warp per node; lane owns 4 channels of h during aggregation, then 2 output cols.
__global__ void __launch_bounds__(256) aggregate_gemm_kernel(
    const __half* __restrict__ P, const int* __restrict__ offs,
    const int* __restrict__ srcs, const float* __restrict__ b0,
    const float* __restrict__ W1, const float* __restrict__ b1,
    float* __restrict__ x)
{
    __shared__ float W1S[128 * 64];   // 32 KB
    __shared__ float HSH[8 * 128];    // per-warp h
    __shared__ float B0S[128];
    __shared__ float B1S[64];
    const int tid = threadIdx.x;
    const int wid = tid >> 5, lane = tid & 31;

    // stage W1, b0, b1 once per block
#pragma unroll
    for (int i = 0; i < 8; i++)
        ((float4*)W1S)[tid + i * 256] = ((const float4*)W1)[tid + i * 256];
    if (tid < 32) ((float4*)B0S)[tid] = ((const float4*)b0)[tid];
    else if (tid < 48) ((float4*)B1S)[tid - 32] = ((const float4*)b1)[tid - 32];
    __syncthreads();

    const int n = blockIdx.x * 8 + wid;
    if (n >= NN) return;

    const uint2* P4 = (const uint2*)P;   // half4 chunks; row = 64 chunks
    // pb = Pb[n] + b0 (lane's 4 channels)
    float pbx, pby, pbz, pbw;
    h4_to_f4(__ldg(P4 + (size_t)n * 64 + 32 + lane), pbx, pby, pbz, pbw);
    float4 b0v = *(const float4*)&B0S[lane * 4];
    pbx += b0v.x; pby += b0v.y; pbz += b0v.z; pbw += b0v.w;

    const int beg = offs[n], end = offs[n + 1];
    float ax, ay, az, aw;
    float4 acc = make_float4(0.f, 0.f, 0.f, 0.f);
    int i = beg;
    for (; i + 4 <= end; i += 4) {
        int s0 = srcs[i], s1 = srcs[i + 1], s2 = srcs[i + 2], s3 = srcs[i + 3];
        uint2 u0 = __ldg(P4 + (size_t)s0 * 64 + lane);
        uint2 u1 = __ldg(P4 + (size_t)s1 * 64 + lane);
        uint2 u2 = __ldg(P4 + (size_t)s2 * 64 + lane);
        uint2 u3 = __ldg(P4 + (size_t)s3 * 64 + lane);
        h4_to_f4(u0, ax, ay, az, aw);
        acc.x += lrelu(ax + pbx); acc.y += lrelu(ay + pby);
        acc.z += lrelu(az + pbz); acc.w += lrelu(aw + pbw);
        h4_to_f4(u1, ax, ay, az, aw);
        acc.x += lrelu(ax + pbx); acc.y += lrelu(ay + pby);
        acc.z += lrelu(az + pbz); acc.w += lrelu(aw + pbw);
        h4_to_f4(u2, ax, ay, az, aw);
        acc.x += lrelu(ax + pbx); acc.y += lrelu(ay + pby);
        acc.z += lrelu(az + pbz); acc.w += lrelu(aw + pbw);
        h4_to_f4(u3, ax, ay, az, aw);
        acc.x += lrelu(ax + pbx); acc.y += lrelu(ay + pby);
        acc.z += lrelu(az + pbz); acc.w += lrelu(aw + pbw);
    }
    for (; i < end; i++) {
        int s = srcs[i];
        h4_to_f4(__ldg(P4 + (size_t)s * 64 + lane), ax, ay, az, aw);
        acc.x += lrelu(ax + pbx); acc.y += lrelu(ay + pby);
        acc.z += lrelu(az + pbz); acc.w += lrelu(aw + pbw);
    }
    *(float4*)&HSH[wid * 128 + lane * 4] = acc;
    __syncwarp();

    // x[n][2*lane], x[n][2*lane+1] = h @ W1 cols, packed f32x2
    const float* h = &HSH[wid * 128];
    unsigned long long s2 = 0ull;
#pragma unroll 8
    for (int k = 0; k < 128; k++) {
        unsigned long long wv = *(const unsigned long long*)&W1S[k * 64 + lane * 2];
        s2 = ffma2(pack2(h[k]), wv, s2);
    }
    float s0f, s1f;
    unpack2(s2, s0f, s1f);
    int deg = end - beg;
    float inv = 1.f / fmaxf((float)deg, 1.f);
    float bf = deg > 0 ? 1.f : 0.f;
    float2 bv = *(const float2*)&B1S[lane * 2];
    *(float2*)&x[(size_t)n * 64 + lane * 2] =
        make_float2(s0f * inv + bv.x * bf, s1f * inv + bv.y * bf);
}

// ------------------------------------------------------------------
// merged edge kernel: per tile of 64 pairs (P tables in fp16)
#define EF_W1   0
#define EF_HD1  17408
#define EF_HS1  25856
#define EF_W12  34304
#define EF_B0A  35872
#define EF_B0B  36000
#define EF_WA3  36128
#define EF_WG3  36132
#define EF_CCV  36136
#define EF_SPI  36160
#define EF_DPI  36224
#define EF_RED  36288
#define EF_TOT  36304
#define EF_NTILE 12500
#define W12(k) ((k) * 12 + (((k) >> 5) << 2))

__global__ void __launch_bounds__(512) edge_fused_kernel(
    const __half* __restrict__ PB, const __half* __restrict__ PA2,
    const int* __restrict__ ei,
    const float* __restrict__ act, const float* __restrict__ ang,
    const float* __restrict__ b0B, const float* __restrict__ b0A,
    const float* __restrict__ W1,
    const float* __restrict__ Wc2, const float* __restrict__ W1e2,
    const float* __restrict__ Wcc,
    const float* __restrict__ wa3, const float* __restrict__ wg3,
    const float* __restrict__ ccv,
    float* __restrict__ out, double* __restrict__ lossp)
{
    extern __shared__ float sm[];
    float* W1S = sm + EF_W1;     // [128][136] tf32
    float* HD1 = sm + EF_HD1;    // [64][132] tf32
    float* HS1 = sm + EF_HS1;    // [64][132] fp32
    float* W12S = sm + EF_W12;   // 128 x 12 (9 used) skewed
    float* B0A = sm + EF_B0A;
    float* B0B = sm + EF_B0B;
    float* WA3 = sm + EF_WA3;
    float* WG3 = sm + EF_WG3;
    float* CCV = sm + EF_CCV;
    int* SP = (int*)(sm + EF_SPI);
    int* DP = (int*)(sm + EF_DPI);
    float* RED = sm + EF_RED;
    const int tid = threadIdx.x;

    for (int i = tid; i < 16384; i += 512) {
        int k = i >> 7, n = i & 127;
        W1S[k * 136 + n] = __uint_as_float(tf32_bits(W1[i]));
    }
    for (int i = tid; i < 1152; i += 512) {
        int k = i / 9, c = i % 9;
        float v = (c < 3) ? Wc2[k * 3 + c]
                : (c < 6) ? W1e2[k * 3 + (c - 3)]
                          : Wcc[k * 3 + (c - 6)];
        W12S[W12(k) + c] = v;
    }
    if (tid < 32) ((float4*)B0A)[tid] = ((const float4*)b0A)[tid];
    else if (tid < 64) ((float4*)B0B)[tid - 32] = ((const float4*)b0B)[tid - 32];
    if (tid < 3) { WA3[tid] = wa3[tid]; WG3[tid] = wg3[tid]; CCV[tid] = ccv[tid]; }

    const int w = tid >> 5, lane = tid & 31;
    const int group = w >> 3;                 // 0: matvec warps, 1: MMA warps
    const int wi = w & 7, gid = lane >> 2, tig = lane & 3;
    const int m0 = (wi & 3) * 16, n0 = (wi >> 2) * 64;
    const int p = (tid & 255) >> 2, q = tid & 3;
    float lsum = 0.f;

    for (int tile = blockIdx.x; tile < EF_NTILE; tile += gridDim.x) {
        const int pbase = tile * 64;
        __syncthreads();
        if (tid < 64) {
            SP[tid] = ei[pbase + tid];
            DP[tid] = ei[NP + pbase + tid];
        }
        __syncthreads();

#pragma unroll
        for (int it = 0; it < 4; it++) {
            int idx = tid + it * 512;
            int r = idx >> 5, c4 = idx & 31;
            int s = SP[r], d = DP[r];
            const uint2* Ps = (const uint2*)(PB + (size_t)s * 256);
            const uint2* Pd = (const uint2*)(PB + (size_t)d * 256);
            float a1x, a1y, a1z, a1w, b1x, b1y, b1z, b1w;
            float a2x, a2y, a2z, a2w, b2x, b2y, b2z, b2w;
            h4_to_f4(__ldg(Ps + c4),      a1x, a1y, a1z, a1w);
            h4_to_f4(__ldg(Pd + 32 + c4), b1x, b1y, b1z, b1w);
            h4_to_f4(__ldg(Pd + c4),      a2x, a2y, a2z, a2w);
            h4_to_f4(__ldg(Ps + 32 + c4), b2x, b2y, b2z, b2w);
            float4 b0v = *(const float4*)&B0B[c4 * 4];
            float h1, h2;
            float4 hs, hd;
            h1 = lrelu(a1x + b1x + b0v.x); h2 = lrelu(a2x + b2x + b0v.x);
            hs.x = h1 + h2; hd.x = __uint_as_float(tf32_bits(h1 - h2));
            h1 = lrelu(a1y + b1y + b0v.y); h2 = lrelu(a2y + b2y + b0v.y);
            hs.y = h1 + h2; hd.y = __uint_as_float(tf32_bits(h1 - h2));
            h1 = lrelu(a1z + b1z + b0v.z); h2 = lrelu(a2z + b2z + b0v.z);
            hs.z = h1 + h2; hd.z = __uint_as_float(tf32_bits(h1 - h2));
            h1 = lrelu(a1w + b1w + b0v.w); h2 = lrelu(a2w + b2w + b0v.w);
            hs.w = h1 + h2; hd.w = __uint_as_float(tf32_bits(h1 - h2));
            *(float4*)&HS1[r * 132 + c4 * 4] = hs;
            *(float4*)&HD1[r * 132 + c4 * 4] = hd;
        }
        __syncthreads();

        if (group == 1) {
            float c[8][4];
#pragma unroll
            for (int nt = 0; nt < 8; nt++)
#pragma unroll
                for (int j = 0; j < 4; j++) c[nt][j] = 0.f;
#pragma unroll 4
            for (int ks = 0; ks < 16; ks++) {
                int k = ks * 8;
                unsigned a0 = __float_as_uint(HD1[(m0 + gid) * 132 + k + tig]);
                unsigned a1 = __float_as_uint(HD1[(m0 + 8 + gid) * 132 + k + tig]);
                unsigned a2 = __float_as_uint(HD1[(m0 + gid) * 132 + k + 4 + tig]);
                unsigned a3 = __float_as_uint(HD1[(m0 + 8 + gid) * 132 + k + 4 + tig]);
#pragma unroll
                for (int nt = 0; nt < 8; nt++) {
                    unsigned b0f = __float_as_uint(W1S[(k + tig) * 136 + n0 + nt * 8 + gid]);
                    unsigned b1f = __float_as_uint(W1S[(k + 4 + tig) * 136 + n0 + nt * 8 + gid]);
                    mma_tf32(c[nt], a0, a1, a2, a3, b0f, b1f);
                }
            }
#pragma unroll
            for (int nt = 0; nt < 8; nt++)
#pragma unroll
                for (int j = 0; j < 4; j++) lsum += c[nt][j] * c[nt][j];
        } else {
            const int gp = pbase + p;
            const int s = SP[p], d = DP[p];
            const uint2* Ps = (const uint2*)(PA2 + (size_t)s * 256);
            const uint2* Pd = (const uint2*)(PA2 + (size_t)d * 256);
            float o0 = 0.f, o1 = 0.f, o2 = 0.f, t0 = 0.f, t1 = 0.f, t2 = 0.f;
#pragma unroll
            for (int c8 = 0; c8 < 8; c8++) {
                int c4 = q * 8 + c8;
                float av1[4], bv1[4], av2[4], bv2[4];
                h4_to_f4(__ldg(Ps + c4),      av1[0], av1[1], av1[2], av1[3]);
                h4_to_f4(__ldg(Pd + 32 + c4), bv1[0], bv1[1], bv1[2], bv1[3]);
                h4_to_f4(__ldg(Pd + c4),      av2[0], av2[1], av2[2], av2[3]);
                h4_to_f4(__ldg(Ps + 32 + c4), bv2[0], bv2[1], bv2[2], bv2[3]);
                float4 hv = *(const float4*)&HS1[p * 132 + c4 * 4];
                float4 b0v = *(const float4*)&B0A[c4 * 4];
                float hsv[4] = {hv.x, hv.y, hv.z, hv.w};
                float b0a[4] = {b0v.x, b0v.y, b0v.z, b0v.w};
#pragma unroll
                for (int j = 0; j < 4; j++) {
                    int k = c4 * 4 + j;
                    float h1 = lrelu(av1[j] + bv1[j] + b0a[j]);
                    float h2 = lrelu(av2[j] + bv2[j] + b0a[j]);
                    float hs = h1 + h2, hd = h1 - h2, f = hsv[j];
                    const float* wv = &W12S[W12(k)];
                    o0 += hs * wv[0] + f * wv[6];
                    o1 += hs * wv[1] + f * wv[7];
                    o2 += hs * wv[2] + f * wv[8];
                    t0 += hd * wv[3];
                    t1 += hd * wv[4];
                    t2 += hd * wv[5];
                }
            }
#pragma unroll
            for (int off = 2; off > 0; off >>= 1) {
                o0 += __shfl_down_sync(0xffffffffu, o0, off, 4);
                o1 += __shfl_down_sync(0xffffffffu, o1, off, 4);
                o2 += __shfl_down_sync(0xffffffffu, o2, off, 4);
                t0 += __shfl_down_sync(0xffffffffu, t0, off, 4);
                t1 += __shfl_down_sync(0xffffffffu, t1, off, 4);
                t2 += __shfl_down_sync(0xffffffffu, t2, off, 4);
            }
            if (q == 0) {
                float av = __ldg(act + gp), gv = __ldg(ang + gp);
                out[(size_t)gp * 3 + 0] = o0 + av * WA3[0] + gv * WG3[0] + CCV[0];
                out[(size_t)gp * 3 + 1] = o1 + av * WA3[1] + gv * WG3[1] + CCV[1];
                out[(size_t)gp * 3 + 2] = o2 + av * WA3[2] + gv * WG3[2] + CCV[2];
                lsum += t0 * t0 + t1 * t1 + t2 * t2;
            }
        }
    }

#pragma unroll
    for (int o = 16; o > 0; o >>= 1) lsum += __shfl_down_sync(0xffffffffu, lsum, o);
    __syncthreads();
    if (lane == 0) RED[w] = lsum;
    __syncthreads();
    if (tid == 0) {
        float l2 = 0.f, l1 = 0.f;
#pragma unroll
        for (int ww = 0; ww < 8; ww++)  l2 += RED[ww];
#pragma unroll
        for (int ww = 8; ww < 16; ww++) l1 += RED[ww];
        atomicAdd(&lossp[0], (double)l1);
        atomicAdd(&lossp[1], (double)l2);
    }
}

// ------------------------------------------------------------------
__global__ void finalize_kernel(float* __restrict__ out, int idx)
{
    double l = 0.5 * (g_loss[0] / (800000.0 * 128.0) + g_loss[1] / (800000.0 * 3.0));
    out[idx] = (float)l;
}

// ------------------------------------------------------------------
extern "C" void kernel_launch(void* const* d_in, const int* in_sizes, int n_in,
                              void* d_out, int out_size)
{
    (void)in_sizes; (void)n_in;
    const float* xnf  = (const float*)d_in[0];
    const int*   ei   = (const int*)d_in[1];
    const float* ang  = (const float*)d_in[2];
    const float* act  = (const float*)d_in[3];
    const float* nc1W0 = (const float*)d_in[5];
    const float* nc1b0 = (const float*)d_in[6];
    const float* nc1W1 = (const float*)d_in[7];
    const float* nc1b1 = (const float*)d_in[8];
    const float* ec1W0 = (const float*)d_in[9];
    const float* ec1b0 = (const float*)d_in[10];
    const float* ec1W1 = (const float*)d_in[11];
    const float* ec1b1 = (const float*)d_in[12];
    const float* ec1Wl = (const float*)d_in[13];
    const float* ec1bl = (const float*)d_in[14];
    const float* nc2W0 = (const float*)d_in[15];
    const float* nc2b0 = (const float*)d_in[16];
    const float* nc2W1 = (const float*)d_in[17];
    const float* nc2b1 = (const float*)d_in[18];
    const float* ec2W0 = (const float*)d_in[19];
    const float* ec2b0 = (const float*)d_in[20];
    const float* ec2W1 = (const float*)d_in[21];
    const float* ec2b1 = (const float*)d_in[22];
    const float* ec2Wl = (const float*)d_in[23];
    const float* ec2bl = (const float*)d_in[24];
    float* out = (float*)d_out;

    float *x1, *x2, *Wc, *c0, *Wc2, *c2, *Wcc, *wa3, *wg3, *cc;
    __half *PA, *PB;
    int *cnt, *offs, *cur, *srcs;
    double* loss;
    cudaGetSymbolAddress((void**)&x1,   g_x1);
    cudaGetSymbolAddress((void**)&x2,   g_x2);
    cudaGetSymbolAddress((void**)&PA,   g_PA);
    cudaGetSymbolAddress((void**)&PB,   g_PB);
    cudaGetSymbolAddress((void**)&Wc,   g_Wc);
    cudaGetSymbolAddress((void**)&c0,   g_c0);
    cudaGetSymbolAddress((void**)&Wc2,  g_Wc2);
    cudaGetSymbolAddress((void**)&c2,   g_c2);
    cudaGetSymbolAddress((void**)&Wcc,  g_Wcc);
    cudaGetSymbolAddress((void**)&wa3,  g_wa3);
    cudaGetSymbolAddress((void**)&wg3,  g_wg3);
    cudaGetSymbolAddress((void**)&cc,   g_cc);
    cudaGetSymbolAddress((void**)&cnt,  g_cnt);
    cudaGetSymbolAddress((void**)&offs, g_offs);
    cudaGetSymbolAddress((void**)&cur,  g_cur);
    cudaGetSymbolAddress((void**)&srcs, g_srcs);
    cudaGetSymbolAddress((void**)&loss, g_loss);

    // Set the smem attribute ONCE, outside graph capture (first call is the
    // pre-capture correctness run). Calling it during capture kills the run.
    static int attr_done = 0;
    if (!attr_done) {
        cudaFuncSetAttribute(edge_fused_kernel,
                             cudaFuncAttributeMaxDynamicSharedMemorySize,
                             EF_TOT * sizeof(float));
        attr_done = 1;
    }

    cudaMemsetAsync(cnt, 0, (size_t)NN * sizeof(int));
    cudaMemsetAsync(cur, 0, (size_t)NN * sizeof(int));
    cudaMemsetAsync(loss, 0, 2 * sizeof(double));

    const int NB64 = (NN + 63) / 64;
    const int NAGG = (NN + 7) / 8;

    // CSR build
    count_kernel<<<(NE + 255) / 256, 256>>>(ei, cnt);
    scan_kernel<<<1, 1024>>>(cnt, offs);
    fill_kernel<<<(NE + 255) / 256, 256>>>(ei, offs, cur, srcs);

    // weight fusions
    fuseA_kernel<<<64, 256>>>(ec1W1, ec1Wl, Wc);
    fuseA2_kernel<<<1, 128>>>(ec1Wl, ec1b1, ec1bl, c0);
    fuseB_kernel<<<1, 384>>>(ec2W1, ec2Wl, ec2b1, ec2bl, Wc2, c2);
    fuseC_kernel<<<1, 384>>>(Wc, c0, ec1Wl, ec2Wl, c2, Wcc, wa3, wg3, cc);

    // ---- conv layer 1 (node) ----
    node_proj_kernel<<<NB64, 256>>>(xnf, nc1W0, PA);
    aggregate_gemm_kernel<<<NAGG, 256>>>(PA, offs, srcs, nc1b0, nc1W1, nc1b1, x1);

    // ---- projection for edge conv 1 ----
    node_proj_kernel<<<NB64, 256>>>(x1, ec1W0, PB);

    // ---- conv layer 2 (node) ----
    node_proj_kernel<<<NB64, 256>>>(x1, nc2W0, PA);
    aggregate_gemm_kernel<<<NAGG, 256>>>(PA, offs, srcs, nc2b0, nc2W1, nc2b1, x2);

    // ---- projection for edge conv 2 (reuses PA) ----
    node_proj_kernel<<<NB64, 256>>>(x2, ec2W0, PA);

    // ---- merged edge convs ----
    edge_fused_kernel<<<148, 512, EF_TOT * sizeof(float)>>>(
        PB, PA, ei, act, ang, ec1b0, ec2b0, ec1W1,
        Wc2, ec2W1, Wcc, wa3, wg3, cc, out, loss);

    finalize_kernel<<<1, 1>>>(out, out_size - 1);
}

// round 11
// speedup vs baseline: 1.0558x; 1.0558x over previous
#include <cuda_runtime.h>
#include <cuda_fp16.h>

#define NN 50000
#define NP 800000   // undirected pairs
#define NE 1600000  // directed edges

// ---------------- scratch (static device globals; no allocations) ----------------
__device__ float  g_x1[NN * 64];
__device__ float  g_x2[NN * 64];
__device__ int    g_cnt[NN];
__device__ int    g_offs[NN + 1];
__device__ int    g_cur[NN];
__device__ int    g_srcs[NE];
__device__ __half g_PA[NN * 256];     // fp16 projection table A (conv1/conv2/ec2)
__device__ __half g_PB[NN * 256];     // fp16 projection table B (ec1)
__device__ float  g_Wc[16384];        // ec1: W1 @ Wl[0:128]
__device__ float  g_c0[128];          // ec1: b1 @ Wl[0:128] + bl
__device__ float  g_Wc2[384];         // ec2: 0.5 * W1e2 @ Wl2[0:3]
__device__ float  g_c2[4];            // ec2: b1e2 @ Wl2[0:3] + bl2
__device__ float  g_Wcc[384];         // 0.5 * Wc @ WlB   (fe1 folded into ec2)
__device__ float  g_wa3[4];           // wl128 @ WlB
__device__ float  g_wg3[4];           // wl129 @ WlB
__device__ float  g_cc[4];            // c0 @ WlB + c2
__device__ double g_loss[2];

__device__ __forceinline__ float lrelu(float z) { return z > 0.f ? z : 0.01f * z; }

// fp16 MMA m16n8k16 (same 10-bit mantissa as tf32; half the MMAs)
__device__ __forceinline__ void mma_f16(float c[4],
    unsigned a0, unsigned a1, unsigned a2, unsigned a3,
    unsigned b0, unsigned b1)
{
    asm volatile(
        "mma.sync.aligned.m16n8k16.row.col.f32.f16.f16.f32 "
        "{%0,%1,%2,%3}, {%4,%5,%6,%7}, {%8,%9}, {%0,%1,%2,%3};"
        : "+f"(c[0]), "+f"(c[1]), "+f"(c[2]), "+f"(c[3])
        : "r"(a0), "r"(a1), "r"(a2), "r"(a3), "r"(b0), "r"(b1));
}

// ---------------- packed f32x2 helpers ----------------
__device__ __forceinline__ unsigned long long pack2(float x)
{
    unsigned long long r;
    asm("mov.b64 %0, {%1, %1};" : "=l"(r) : "f"(x));
    return r;
}
__device__ __forceinline__ unsigned long long ffma2(
    unsigned long long a, unsigned long long b, unsigned long long c)
{
    unsigned long long d;
    asm("fma.rn.f32x2 %0, %1, %2, %3;" : "=l"(d) : "l"(a), "l"(b), "l"(c));
    return d;
}
__device__ __forceinline__ void unpack2(unsigned long long v, float& lo, float& hi)
{
    asm("mov.b64 {%0, %1}, %2;" : "=f"(lo), "=f"(hi) : "l"(v));
}

// half4 (uint2) -> 4 floats
__device__ __forceinline__ void h4_to_f4(uint2 u, float& f0, float& f1, float& f2, float& f3)
{
    __half2 p01 = *(__half2*)&u.x;
    __half2 p23 = *(__half2*)&u.y;
    float2 a = __half22float2(p01);
    float2 b = __half22float2(p23);
    f0 = a.x; f1 = a.y; f2 = b.x; f3 = b.y;
}

// ------------------------------------------------------------------
// Fused weight-precompute: blocks 0..42 compute Wc (ec1 W1@Wl), block 43 does
// c0, Wc2, c2.
__global__ void __launch_bounds__(384) fuseAB_kernel(
    const float* __restrict__ W1, const float* __restrict__ Wl,
    const float* __restrict__ b1, const float* __restrict__ bl,
    const float* __restrict__ W1e2, const float* __restrict__ Wl2,
    const float* __restrict__ b1e2, const float* __restrict__ bl2,
    float* __restrict__ Wc, float* __restrict__ c0,
    float* __restrict__ Wc2, float* __restrict__ c2)
{
    const int b = blockIdx.x, t = threadIdx.x;
    if (b < 43) {
        int id = b * 384 + t;
        if (id < 16384) {
            int r = id >> 7, c = id & 127;
            float s = 0.f;
#pragma unroll 8
            for (int k = 0; k < 128; k++) s += W1[r * 128 + k] * Wl[k * 128 + c];
            Wc[id] = s;
        }
    } else {
        if (t < 128) {
            float s = bl[t];
#pragma unroll 8
            for (int k = 0; k < 128; k++) s += b1[k] * Wl[k * 128 + t];
            c0[t] = s;
        }
        {
            int k = t / 3, c = t % 3;
            Wc2[t] = 0.5f * (W1e2[k * 3 + 0] * Wl2[0 + c] +
                             W1e2[k * 3 + 1] * Wl2[3 + c] +
                             W1e2[k * 3 + 2] * Wl2[6 + c]);
        }
        if (t < 3)
            c2[t] = b1e2[0] * Wl2[0 + t] + b1e2[1] * Wl2[3 + t] +
                    b1e2[2] * Wl2[6 + t] + bl2[t];
    }
}
// Wcc = 0.5 * Wc @ WlB ; wa3/wg3 = Wl rows 128/129 @ WlB ; cc = c0 @ WlB + c2
__global__ void fuseC_kernel(const float* __restrict__ Wc, const float* __restrict__ c0,
                             const float* __restrict__ Wl1, const float* __restrict__ Wl2,
                             const float* __restrict__ c2,
                             float* __restrict__ Wcc, float* __restrict__ wa3,
                             float* __restrict__ wg3, float* __restrict__ cc)
{
    int id = threadIdx.x;   // 384
    int k = id / 3, c = id % 3;
    float s = 0.f;
#pragma unroll 8
    for (int j = 0; j < 128; j++) s += Wc[k * 128 + j] * Wl2[(3 + j) * 3 + c];
    Wcc[id] = 0.5f * s;
    if (id < 3) {
        float sa = 0.f, sg = 0.f, sc = 0.f;
        for (int j = 0; j < 128; j++) {
            float wb = Wl2[(3 + j) * 3 + id];
            sa += Wl1[128 * 128 + j] * wb;
            sg += Wl1[129 * 128 + j] * wb;
            sc += c0[j] * wb;
        }
        wa3[id] = sa; wg3[id] = sg; cc[id] = sc + c2[id];
    }
}

// ------------------------------------------------------------------
// CSR build: count (dst degrees) -> scan -> fill
__global__ void count_kernel(const int* __restrict__ ei, int* __restrict__ cnt)
{
    int e = blockIdx.x * blockDim.x + threadIdx.x;
    if (e < NE) atomicAdd(&cnt[ei[NE + e]], 1);
}

__global__ void __launch_bounds__(1024) scan_kernel(const int* __restrict__ cnt,
                                                    int* __restrict__ offs)
{
    __shared__ int part[1024];
    const int t = threadIdx.x;
    const int CH = (NN + 1023) / 1024;   // 49
    const int base = t * CH;
    int s = 0;
    for (int j = 0; j < CH; j++) {
        int n = base + j;
        if (n < NN) s += cnt[n];
    }
    part[t] = s;
    __syncthreads();
    for (int off = 1; off < 1024; off <<= 1) {
        int v = (t >= off) ? part[t - off] : 0;
        __syncthreads();
        part[t] += v;
        __syncthreads();
    }
    int run = part[t] - s;
    for (int j = 0; j < CH; j++) {
        int n = base + j;
        if (n < NN) { offs[n] = run; run += cnt[n]; }
    }
    if (t == 1023) offs[NN] = part[1023];
}

__global__ void fill_kernel(const int* __restrict__ ei, const int* __restrict__ offs,
                            int* __restrict__ cur, int* __restrict__ srcs)
{
    int e = blockIdx.x * blockDim.x + threadIdx.x;
    if (e < NE) {
        int src = ei[e];
        int dst = ei[NE + e];
        int pos = atomicAdd(&cur[dst], 1);
        srcs[offs[dst] + pos] = src;
    }
}

// ------------------------------------------------------------------
// node_proj: P[n][0..127] = x[n] @ W0[0:64,:] ; P[n][128..255] = x[n] @ W0[64:128,:]
__global__ void __launch_bounds__(256) node_proj_kernel(
    const float* __restrict__ x, const float* __restrict__ W0, __half* __restrict__ Ph)
{
    __shared__ float XT[64 * 68];
    __shared__ float WC[16 * 256];
    const int tid = threadIdx.x;
    const int nbase = blockIdx.x * 64;
#pragma unroll
    for (int i = 0; i < 4; i++) {
        int lin = tid * 4 + i;
        int r = lin >> 4, q = lin & 15;
        int node = nbase + r; if (node >= NN) node = NN - 1;
        float4 v = __ldg((const float4*)x + (size_t)node * 16 + q);
        XT[(q * 4 + 0) * 68 + r] = v.x;
        XT[(q * 4 + 1) * 68 + r] = v.y;
        XT[(q * 4 + 2) * 68 + r] = v.z;
        XT[(q * 4 + 3) * 68 + r] = v.w;
    }
    unsigned long long acc2[8][4];
#pragma unroll
    for (int i = 0; i < 8; i++)
#pragma unroll
        for (int j = 0; j < 4; j++) acc2[i][j] = 0ull;
    const int tr = tid >> 5, tc = tid & 31;
    for (int kc = 0; kc < 64; kc += 16) {
        __syncthreads();
#pragma unroll
        for (int i = 0; i < 4; i++) {
            int lin = tid + i * 256;
            int kk = lin >> 6, j4 = lin & 63;
            int j = j4 * 4;
            const float* src = (j < 128) ? (W0 + (kc + kk) * 128 + j)
                                         : (W0 + (64 + kc + kk) * 128 + (j - 128));
            *(float4*)&WC[kk * 256 + j] = *(const float4*)src;
        }
        __syncthreads();
#pragma unroll
        for (int kk = 0; kk < 16; kk++) {
            float4 a0 = *(const float4*)&XT[(kc + kk) * 68 + tr * 8];
            float4 a1 = *(const float4*)&XT[(kc + kk) * 68 + tr * 8 + 4];
            ulonglong2 w01 = *(const ulonglong2*)&WC[kk * 256 + tc * 8];
            ulonglong2 w23 = *(const ulonglong2*)&WC[kk * 256 + tc * 8 + 4];
            float a[8] = {a0.x, a0.y, a0.z, a0.w, a1.x, a1.y, a1.z, a1.w};
#pragma unroll
            for (int i = 0; i < 8; i++) {
                unsigned long long ap = pack2(a[i]);
                acc2[i][0] = ffma2(ap, w01.x, acc2[i][0]);
                acc2[i][1] = ffma2(ap, w01.y, acc2[i][1]);
                acc2[i][2] = ffma2(ap, w23.x, acc2[i][2]);
                acc2[i][3] = ffma2(ap, w23.y, acc2[i][3]);
            }
        }
    }
#pragma unroll
    for (int i = 0; i < 8; i++) {
        int node = nbase + tr * 8 + i;
        if (node < NN) {
            float o[8];
#pragma unroll
            for (int j = 0; j < 4; j++) unpack2(acc2[i][j], o[2 * j], o[2 * j + 1]);
            __half2 h0 = __floats2half2_rn(o[0], o[1]);
            __half2 h1 = __floats2half2_rn(o[2], o[3]);
            __half2 h2 = __floats2half2_rn(o[4], o[5]);
            __half2 h3 = __floats2half2_rn(o[6], o[7]);
            uint4 v;
            v.x = *(unsigned*)&h0; v.y = *(unsigned*)&h1;
            v.z = *(unsigned*)&h2; v.w = *(unsigned*)&h3;
            *(uint4*)&Ph[(size_t)node * 256 + tc * 8] = v;
        }
    }
}

// ------------------------------------------------------------------
// Fused CSR aggregation + per-node GEMM (unchanged from R10)
__global__ void __launch_bounds__(256) aggregate_gemm_kernel(
    const __half* __restrict__ P, const int* __restrict__ offs,
    const int* __restrict__ srcs, const float* __restrict__ b0,
    const float* __restrict__ W1, const float* __restrict__ b1,
    float* __restrict__ x)
{
    __shared__ float W1S[128 * 64];
    __shared__ float HSH[8 * 128];
    __shared__ float B0S[128];
    __shared__ float B1S[64];
    const int tid = threadIdx.x;
    const int wid = tid >> 5, lane = tid & 31;

#pragma unroll
    for (int i = 0; i < 8; i++)
        ((float4*)W1S)[tid + i * 256] = ((const float4*)W1)[tid + i * 256];
    if (tid < 32) ((float4*)B0S)[tid] = ((const float4*)b0)[tid];
    else if (tid < 48) ((float4*)B1S)[tid - 32] = ((const float4*)b1)[tid - 32];
    __syncthreads();

    const int n = blockIdx.x * 8 + wid;
    if (n >= NN) return;

    const uint2* P4 = (const uint2*)P;
    float pbx, pby, pbz, pbw;
    h4_to_f4(__ldg(P4 + (size_t)n * 64 + 32 + lane), pbx, pby, pbz, pbw);
    float4 b0v = *(const float4*)&B0S[lane * 4];
    pbx += b0v.x; pby += b0v.y; pbz += b0v.z; pbw += b0v.w;

    const int beg = offs[n], end = offs[n + 1];
    float ax, ay, az, aw;
    float4 acc = make_float4(0.f, 0.f, 0.f, 0.f);
    int i = beg;
    for (; i + 4 <= end; i += 4) {
        int s0 = srcs[i], s1 = srcs[i + 1], s2 = srcs[i + 2], s3 = srcs[i + 3];
        uint2 u0 = __ldg(P4 + (size_t)s0 * 64 + lane);
        uint2 u1 = __ldg(P4 + (size_t)s1 * 64 + lane);
        uint2 u2 = __ldg(P4 + (size_t)s2 * 64 + lane);
        uint2 u3 = __ldg(P4 + (size_t)s3 * 64 + lane);
        h4_to_f4(u0, ax, ay, az, aw);
        acc.x += lrelu(ax + pbx); acc.y += lrelu(ay + pby);
        acc.z += lrelu(az + pbz); acc.w += lrelu(aw + pbw);
        h4_to_f4(u1, ax, ay, az, aw);
        acc.x += lrelu(ax + pbx); acc.y += lrelu(ay + pby);
        acc.z += lrelu(az + pbz); acc.w += lrelu(aw + pbw);
        h4_to_f4(u2, ax, ay, az, aw);
        acc.x += lrelu(ax + pbx); acc.y += lrelu(ay + pby);
        acc.z += lrelu(az + pbz); acc.w += lrelu(aw + pbw);
        h4_to_f4(u3, ax, ay, az, aw);
        acc.x += lrelu(ax + pbx); acc.y += lrelu(ay + pby);
        acc.z += lrelu(az + pbz); acc.w += lrelu(aw + pbw);
    }
    for (; i < end; i++) {
        int s = srcs[i];
        h4_to_f4(__ldg(P4 + (size_t)s * 64 + lane), ax, ay, az, aw);
        acc.x += lrelu(ax + pbx); acc.y += lrelu(ay + pby);
        acc.z += lrelu(az + pbz); acc.w += lrelu(aw + pbw);
    }
    *(float4*)&HSH[wid * 128 + lane * 4] = acc;
    __syncwarp();

    const float* h = &HSH[wid * 128];
    unsigned long long s2 = 0ull;
#pragma unroll 8
    for (int k = 0; k < 128; k++) {
        unsigned long long wv = *(const unsigned long long*)&W1S[k * 64 + lane * 2];
        s2 = ffma2(pack2(h[k]), wv, s2);
    }
    float s0f, s1f;
    unpack2(s2, s0f, s1f);
    int deg = end - beg;
    float inv = 1.f / fmaxf((float)deg, 1.f);
    float bf = deg > 0 ? 1.f : 0.f;
    float2 bv = *(const float2*)&B1S[lane * 2];
    *(float2*)&x[(size_t)n * 64 + lane * 2] =
        make_float2(s0f * inv + bv.x * bf, s1f * inv + bv.y * bf);
}

// ------------------------------------------------------------------
// merged edge kernel — fp16 W1/HD1, HMMA loss GEMM, 2 blocks/SM (grid 296)
// smem float offsets:
#define EF_W1T  0        // half[128][136] transposed (W1T[n][k]) = 8704 floats
#define EF_HD1  8704     // half[64][132] = 4224 floats
#define EF_HS1  12928    // float[64][132] = 8448
#define EF_W12  21376    // 1568
#define EF_B0A  22944
#define EF_B0B  23072
#define EF_WA3  23200
#define EF_WG3  23208
#define EF_CCV  23216
#define EF_SPI  23232
#define EF_DPI  23296
#define EF_RED  23360
#define EF_TOT  23392
#define EF_GRID 296
#define EF_NTILE 12500
#define W12(k) ((k) * 12 + (((k) >> 5) << 2))

__global__ void __launch_bounds__(512) edge_fused_kernel(
    const __half* __restrict__ PB, const __half* __restrict__ PA2,
    const int* __restrict__ ei,
    const float* __restrict__ act, const float* __restrict__ ang,
    const float* __restrict__ b0B, const float* __restrict__ b0A,
    const float* __restrict__ W1,
    const float* __restrict__ Wc2, const float* __restrict__ W1e2,
    const float* __restrict__ Wcc,
    const float* __restrict__ wa3, const float* __restrict__ wg3,
    const float* __restrict__ ccv,
    float* __restrict__ out, double* __restrict__ lossp)
{
    extern __shared__ float sm[];
    __half* W1T = (__half*)(sm + EF_W1T);   // [n][k] stride 136
    __half* HD1h = (__half*)(sm + EF_HD1);  // [r][k] stride 132
    float* HS1 = sm + EF_HS1;               // [r][c] stride 132
    float* W12S = sm + EF_W12;
    float* B0A = sm + EF_B0A;
    float* B0B = sm + EF_B0B;
    float* WA3 = sm + EF_WA3;
    float* WG3 = sm + EF_WG3;
    float* CCV = sm + EF_CCV;
    int* SP = (int*)(sm + EF_SPI);
    int* DP = (int*)(sm + EF_DPI);
    float* RED = sm + EF_RED;
    const int tid = threadIdx.x;

    // stage weights once
    for (int i = tid; i < 16384; i += 512) {
        int k = i >> 7, n = i & 127;
        W1T[n * 136 + k] = __float2half_rn(W1[i]);
    }
    for (int i = tid; i < 1152; i += 512) {
        int k = i / 9, c = i % 9;
        float v = (c < 3) ? Wc2[k * 3 + c]
                : (c < 6) ? W1e2[k * 3 + (c - 3)]
                          : Wcc[k * 3 + (c - 6)];
        W12S[W12(k) + c] = v;
    }
    if (tid < 32) ((float4*)B0A)[tid] = ((const float4*)b0A)[tid];
    else if (tid < 64) ((float4*)B0B)[tid - 32] = ((const float4*)b0B)[tid - 32];
    if (tid < 3) { WA3[tid] = wa3[tid]; WG3[tid] = wg3[tid]; CCV[tid] = ccv[tid]; }

    const int w = tid >> 5, lane = tid & 31;
    const int group = w >> 3;                 // 0: matvec warps, 1: MMA warps
    const int wi = w & 7, gid = lane >> 2, tig = lane & 3;
    const int m0 = (wi & 3) * 16, n0 = (wi >> 2) * 64;
    const int p = (tid & 255) >> 2, q = tid & 3;
    float lsum = 0.f;

    for (int tile = blockIdx.x; tile < EF_NTILE; tile += EF_GRID) {
        const int pbase = tile * 64;
        __syncthreads();   // previous tile fully consumed
        if (tid < 64) {
            SP[tid] = ei[pbase + tid];
            DP[tid] = ei[NP + pbase + tid];
        }
        __syncthreads();

        // build HS1 (fp32) / HD1 (fp16) from fp16 PB
#pragma unroll
        for (int it = 0; it < 4; it++) {
            int idx = tid + it * 512;
            int r = idx >> 5, c4 = idx & 31;
            int s = SP[r], d = DP[r];
            const uint2* Ps = (const uint2*)(PB + (size_t)s * 256);
            const uint2* Pd = (const uint2*)(PB + (size_t)d * 256);
            float a1x, a1y, a1z, a1w, b1x, b1y, b1z, b1w;
            float a2x, a2y, a2z, a2w, b2x, b2y, b2z, b2w;
            h4_to_f4(__ldg(Ps + c4),      a1x, a1y, a1z, a1w);
            h4_to_f4(__ldg(Pd + 32 + c4), b1x, b1y, b1z, b1w);
            h4_to_f4(__ldg(Pd + c4),      a2x, a2y, a2z, a2w);
            h4_to_f4(__ldg(Ps + 32 + c4), b2x, b2y, b2z, b2w);
            float4 b0v = *(const float4*)&B0B[c4 * 4];
            float h1, h2;
            float4 hs;
            float hdx, hdy, hdz, hdw;
            h1 = lrelu(a1x + b1x + b0v.x); h2 = lrelu(a2x + b2x + b0v.x);
            hs.x = h1 + h2; hdx = h1 - h2;
            h1 = lrelu(a1y + b1y + b0v.y); h2 = lrelu(a2y + b2y + b0v.y);
            hs.y = h1 + h2; hdy = h1 - h2;
            h1 = lrelu(a1z + b1z + b0v.z); h2 = lrelu(a2z + b2z + b0v.z);
            hs.z = h1 + h2; hdz = h1 - h2;
            h1 = lrelu(a1w + b1w + b0v.w); h2 = lrelu(a2w + b2w + b0v.w);
            hs.w = h1 + h2; hdw = h1 - h2;
            *(float4*)&HS1[r * 132 + c4 * 4] = hs;
            __half2 dlo = __floats2half2_rn(hdx, hdy);
            __half2 dhi = __floats2half2_rn(hdz, hdw);
            uint2 du; du.x = *(unsigned*)&dlo; du.y = *(unsigned*)&dhi;
            *(uint2*)&HD1h[r * 132 + c4 * 4] = du;
        }
        __syncthreads();

        if (group == 1) {
            // loss1 GEMM: HD1[64,128] @ W1[128,128] via m16n8k16 fp16
            float c[8][4];
#pragma unroll
            for (int nt = 0; nt < 8; nt++)
#pragma unroll
                for (int j = 0; j < 4; j++) c[nt][j] = 0.f;
#pragma unroll 2
            for (int ks = 0; ks < 8; ks++) {
                int kb = ks * 16;
                unsigned a0 = *(const unsigned*)&HD1h[(m0 + gid) * 132 + kb + 2 * tig];
                unsigned a1 = *(const unsigned*)&HD1h[(m0 + 8 + gid) * 132 + kb + 2 * tig];
                unsigned a2 = *(const unsigned*)&HD1h[(m0 + gid) * 132 + kb + 8 + 2 * tig];
                unsigned a3 = *(const unsigned*)&HD1h[(m0 + 8 + gid) * 132 + kb + 8 + 2 * tig];
#pragma unroll
                for (int nt = 0; nt < 8; nt++) {
                    int n = n0 + nt * 8 + gid;
                    unsigned b0f = *(const unsigned*)&W1T[n * 136 + kb + 2 * tig];
                    unsigned b1f = *(const unsigned*)&W1T[n * 136 + kb + 8 + 2 * tig];
                    mma_f16(c[nt], a0, a1, a2, a3, b0f, b1f);
                }
            }
#pragma unroll
            for (int nt = 0; nt < 8; nt++)
#pragma unroll
                for (int j = 0; j < 4; j++) lsum += c[nt][j] * c[nt][j];
        } else {
            // per-pair matvec path (fp16 PA2 gathers)
            const int gp = pbase + p;
            const int s = SP[p], d = DP[p];
            const uint2* Ps = (const uint2*)(PA2 + (size_t)s * 256);
            const uint2* Pd = (const uint2*)(PA2 + (size_t)d * 256);
            float o0 = 0.f, o1 = 0.f, o2 = 0.f, t0 = 0.f, t1 = 0.f, t2 = 0.f;
#pragma unroll
            for (int c8 = 0; c8 < 8; c8++) {
                int c4 = q * 8 + c8;
                float av1[4], bv1[4], av2[4], bv2[4];
                h4_to_f4(__ldg(Ps + c4),      av1[0], av1[1], av1[2], av1[3]);
                h4_to_f4(__ldg(Pd + 32 + c4), bv1[0], bv1[1], bv1[2], bv1[3]);
                h4_to_f4(__ldg(Pd + c4),      av2[0], av2[1], av2[2], av2[3]);
                h4_to_f4(__ldg(Ps + 32 + c4), bv2[0], bv2[1], bv2[2], bv2[3]);
                float4 hv = *(const float4*)&HS1[p * 132 + c4 * 4];
                float4 b0v = *(const float4*)&B0A[c4 * 4];
                float hsv[4] = {hv.x, hv.y, hv.z, hv.w};
                float b0a[4] = {b0v.x, b0v.y, b0v.z, b0v.w};
#pragma unroll
                for (int j = 0; j < 4; j++) {
                    int k = c4 * 4 + j;
                    float h1 = lrelu(av1[j] + bv1[j] + b0a[j]);
                    float h2 = lrelu(av2[j] + bv2[j] + b0a[j]);
                    float hs = h1 + h2, hd = h1 - h2, f = hsv[j];
                    const float* wv = &W12S[W12(k)];
                    o0 += hs * wv[0] + f * wv[6];
                    o1 += hs * wv[1] + f * wv[7];
                    o2 += hs * wv[2] + f * wv[8];
                    t0 += hd * wv[3];
                    t1 += hd * wv[4];
                    t2 += hd * wv[5];
                }
            }
#pragma unroll
            for (int off = 2; off > 0; off >>= 1) {
                o0 += __shfl_down_sync(0xffffffffu, o0, off, 4);
                o1 += __shfl_down_sync(0xffffffffu, o1, off, 4);
                o2 += __shfl_down_sync(0xffffffffu, o2, off, 4);
                t0 += __shfl_down_sync(0xffffffffu, t0, off, 4);
                t1 += __shfl_down_sync(0xffffffffu, t1, off, 4);
                t2 += __shfl_down_sync(0xffffffffu, t2, off, 4);
            }
            if (q == 0) {
                float av = __ldg(act + gp), gv = __ldg(ang + gp);
                out[(size_t)gp * 3 + 0] = o0 + av * WA3[0] + gv * WG3[0] + CCV[0];
                out[(size_t)gp * 3 + 1] = o1 + av * WA3[1] + gv * WG3[1] + CCV[1];
                out[(size_t)gp * 3 + 2] = o2 + av * WA3[2] + gv * WG3[2] + CCV[2];
                lsum += t0 * t0 + t1 * t1 + t2 * t2;
            }
        }
    }

    // final loss reduce: warps 0-7 hold loss2, warps 8-15 hold loss1
#pragma unroll
    for (int o = 16; o > 0; o >>= 1) lsum += __shfl_down_sync(0xffffffffu, lsum, o);
    __syncthreads();
    if (lane == 0) RED[w] = lsum;
    __syncthreads();
    if (tid == 0) {
        float l2 = 0.f, l1 = 0.f;
#pragma unroll
        for (int ww = 0; ww < 8; ww++)  l2 += RED[ww];
#pragma unroll
        for (int ww = 8; ww < 16; ww++) l1 += RED[ww];
        atomicAdd(&lossp[0], (double)l1);
        atomicAdd(&lossp[1], (double)l2);
    }
}

// ------------------------------------------------------------------
__global__ void finalize_kernel(float* __restrict__ out, int idx)
{
    double l = 0.5 * (g_loss[0] / (800000.0 * 128.0) + g_loss[1] / (800000.0 * 3.0));
    out[idx] = (float)l;
}

// ------------------------------------------------------------------
extern "C" void kernel_launch(void* const* d_in, const int* in_sizes, int n_in,
                              void* d_out, int out_size)
{
    (void)in_sizes; (void)n_in;
    const float* xnf  = (const float*)d_in[0];
    const int*   ei   = (const int*)d_in[1];
    const float* ang  = (const float*)d_in[2];
    const float* act  = (const float*)d_in[3];
    const float* nc1W0 = (const float*)d_in[5];
    const float* nc1b0 = (const float*)d_in[6];
    const float* nc1W1 = (const float*)d_in[7];
    const float* nc1b1 = (const float*)d_in[8];
    const float* ec1W0 = (const float*)d_in[9];
    const float* ec1b0 = (const float*)d_in[10];
    const float* ec1W1 = (const float*)d_in[11];
    const float* ec1b1 = (const float*)d_in[12];
    const float* ec1Wl = (const float*)d_in[13];
    const float* ec1bl = (const float*)d_in[14];
    const float* nc2W0 = (const float*)d_in[15];
    const float* nc2b0 = (const float*)d_in[16];
    const float* nc2W1 = (const float*)d_in[17];
    const float* nc2b1 = (const float*)d_in[18];
    const float* ec2W0 = (const float*)d_in[19];
    const float* ec2b0 = (const float*)d_in[20];
    const float* ec2W1 = (const float*)d_in[21];
    const float* ec2b1 = (const float*)d_in[22];
    const float* ec2Wl = (const float*)d_in[23];
    const float* ec2bl = (const float*)d_in[24];
    float* out = (float*)d_out;

    float *x1, *x2, *Wc, *c0, *Wc2, *c2, *Wcc, *wa3, *wg3, *cc;
    __half *PA, *PB;
    int *cnt, *offs, *cur, *srcs;
    double* loss;
    cudaGetSymbolAddress((void**)&x1,   g_x1);
    cudaGetSymbolAddress((void**)&x2,   g_x2);
    cudaGetSymbolAddress((void**)&PA,   g_PA);
    cudaGetSymbolAddress((void**)&PB,   g_PB);
    cudaGetSymbolAddress((void**)&Wc,   g_Wc);
    cudaGetSymbolAddress((void**)&c0,   g_c0);
    cudaGetSymbolAddress((void**)&Wc2,  g_Wc2);
    cudaGetSymbolAddress((void**)&c2,   g_c2);
    cudaGetSymbolAddress((void**)&Wcc,  g_Wcc);
    cudaGetSymbolAddress((void**)&wa3,  g_wa3);
    cudaGetSymbolAddress((void**)&wg3,  g_wg3);
    cudaGetSymbolAddress((void**)&cc,   g_cc);
    cudaGetSymbolAddress((void**)&cnt,  g_cnt);
    cudaGetSymbolAddress((void**)&offs, g_offs);
    cudaGetSymbolAddress((void**)&cur,  g_cur);
    cudaGetSymbolAddress((void**)&srcs, g_srcs);
    cudaGetSymbolAddress((void**)&loss, g_loss);

    // Set the smem attribute ONCE, outside graph capture (first call is the
    // pre-capture correctness run). Calling it during capture kills the run.
    static int attr_done = 0;
    if (!attr_done) {
        cudaFuncSetAttribute(edge_fused_kernel,
                             cudaFuncAttributeMaxDynamicSharedMemorySize,
                             EF_TOT * sizeof(float));
        attr_done = 1;
    }

    cudaMemsetAsync(cnt, 0, (size_t)NN * sizeof(int));
    cudaMemsetAsync(cur, 0, (size_t)NN * sizeof(int));
    cudaMemsetAsync(loss, 0, 2 * sizeof(double));

    const int NB64 = (NN + 63) / 64;
    const int NAGG = (NN + 7) / 8;

    // CSR build
    count_kernel<<<(NE + 255) / 256, 256>>>(ei, cnt);
    scan_kernel<<<1, 1024>>>(cnt, offs);
    fill_kernel<<<(NE + 255) / 256, 256>>>(ei, offs, cur, srcs);

    // weight fusions (AB merged; C depends on AB)
    fuseAB_kernel<<<44, 384>>>(ec1W1, ec1Wl, ec1b1, ec1bl,
                               ec2W1, ec2Wl, ec2b1, ec2bl,
                               Wc, c0, Wc2, c2);
    fuseC_kernel<<<1, 384>>>(Wc, c0, ec1Wl, ec2Wl, c2, Wcc, wa3, wg3, cc);

    // ---- conv layer 1 (node) ----
    node_proj_kernel<<<NB64, 256>>>(xnf, nc1W0, PA);
    aggregate_gemm_kernel<<<NAGG, 256>>>(PA, offs, srcs, nc1b0, nc1W1, nc1b1, x1);

    // ---- projection for edge conv 1 ----
    node_proj_kernel<<<NB64, 256>>>(x1, ec1W0, PB);

    // ---- conv layer 2 (node) ----
    node_proj_kernel<<<NB64, 256>>>(x1, nc2W0, PA);
    aggregate_gemm_kernel<<<NAGG, 256>>>(PA, offs, srcs, nc2b0, nc2W1, nc2b1, x2);

    // ---- projection for edge conv 2 (reuses PA) ----
    node_proj_kernel<<<NB64, 256>>>(x2, ec2W0, PA);

    // ---- merged edge convs (2 blocks/SM) ----
    edge_fused_kernel<<<EF_GRID, 512, EF_TOT * sizeof(float)>>>(
        PB, PA, ei, act, ang, ec1b0, ec2b0, ec1W1,
        Wc2, ec2W1, Wcc, wa3, wg3, cc, out, loss);

    finalize_kernel<<<1, 1>>>(out, out_size - 1);
}

// round 12
// speedup vs baseline: 1.0988x; 1.0407x over previous
#include <cuda_runtime.h>
#include <cuda_fp16.h>

#define NN 50000
#define NP 800000   // undirected pairs
#define NE 1600000  // directed edges

// ---------------- scratch (static device globals; no allocations) ----------------
__device__ float  g_x1[NN * 64];
__device__ float  g_x2[NN * 64];
__device__ int    g_cnt[NN];
__device__ int    g_offs[NN + 1];
__device__ int    g_cur[NN];
__device__ int    g_srcs[NE];
__device__ __half g_PA[NN * 256];     // fp16 projection table A (conv1/conv2/ec2)
__device__ __half g_PB[NN * 256];     // fp16 projection table B (ec1)
__device__ float  g_Wc[16384];        // ec1: W1 @ Wl[0:128]
__device__ float  g_c0[128];          // ec1: b1 @ Wl[0:128] + bl
__device__ float  g_Wc2[384];         // ec2: 0.5 * W1e2 @ Wl2[0:3]
__device__ float  g_c2[4];            // ec2: b1e2 @ Wl2[0:3] + bl2
__device__ float  g_Wcc[384];         // 0.5 * Wc @ WlB   (fe1 folded into ec2)
__device__ float  g_wa3[4];           // wl128 @ WlB
__device__ float  g_wg3[4];           // wl129 @ WlB
__device__ float  g_cc[4];            // c0 @ WlB + c2
__device__ double g_loss[2];

__device__ __forceinline__ float lrelu(float z) { return z > 0.f ? z : 0.01f * z; }

// fp16 MMA m16n8k16 (same 10-bit mantissa as tf32; half the MMAs)
__device__ __forceinline__ void mma_f16(float c[4],
    unsigned a0, unsigned a1, unsigned a2, unsigned a3,
    unsigned b0, unsigned b1)
{
    asm volatile(
        "mma.sync.aligned.m16n8k16.row.col.f32.f16.f16.f32 "
        "{%0,%1,%2,%3}, {%4,%5,%6,%7}, {%8,%9}, {%0,%1,%2,%3};"
        : "+f"(c[0]), "+f"(c[1]), "+f"(c[2]), "+f"(c[3])
        : "r"(a0), "r"(a1), "r"(a2), "r"(a3), "r"(b0), "r"(b1));
}

// ---------------- packed f32x2 helpers ----------------
__device__ __forceinline__ unsigned long long pack2(float x)
{
    unsigned long long r;
    asm("mov.b64 %0, {%1, %1};" : "=l"(r) : "f"(x));
    return r;
}
__device__ __forceinline__ unsigned long long ffma2(
    unsigned long long a, unsigned long long b, unsigned long long c)
{
    unsigned long long d;
    asm("fma.rn.f32x2 %0, %1, %2, %3;" : "=l"(d) : "l"(a), "l"(b), "l"(c));
    return d;
}
__device__ __forceinline__ void unpack2(unsigned long long v, float& lo, float& hi)
{
    asm("mov.b64 {%0, %1}, %2;" : "=f"(lo), "=f"(hi) : "l"(v));
}

// half4 (uint2) -> 4 floats
__device__ __forceinline__ void h4_to_f4(uint2 u, float& f0, float& f1, float& f2, float& f3)
{
    __half2 p01 = *(__half2*)&u.x;
    __half2 p23 = *(__half2*)&u.y;
    float2 a = __half22float2(p01);
    float2 b = __half22float2(p23);
    f0 = a.x; f1 = a.y; f2 = b.x; f3 = b.y;
}

// ------------------------------------------------------------------
// Fused weight-precompute: blocks 0..42 compute Wc (ec1 W1@Wl), block 43 does
// c0, Wc2, c2.
__global__ void __launch_bounds__(384) fuseAB_kernel(
    const float* __restrict__ W1, const float* __restrict__ Wl,
    const float* __restrict__ b1, const float* __restrict__ bl,
    const float* __restrict__ W1e2, const float* __restrict__ Wl2,
    const float* __restrict__ b1e2, const float* __restrict__ bl2,
    float* __restrict__ Wc, float* __restrict__ c0,
    float* __restrict__ Wc2, float* __restrict__ c2)
{
    const int b = blockIdx.x, t = threadIdx.x;
    if (b < 43) {
        int id = b * 384 + t;
        if (id < 16384) {
            int r = id >> 7, c = id & 127;
            float s = 0.f;
#pragma unroll 8
            for (int k = 0; k < 128; k++) s += W1[r * 128 + k] * Wl[k * 128 + c];
            Wc[id] = s;
        }
    } else {
        if (t < 128) {
            float s = bl[t];
#pragma unroll 8
            for (int k = 0; k < 128; k++) s += b1[k] * Wl[k * 128 + t];
            c0[t] = s;
        }
        {
            int k = t / 3, c = t % 3;
            Wc2[t] = 0.5f * (W1e2[k * 3 + 0] * Wl2[0 + c] +
                             W1e2[k * 3 + 1] * Wl2[3 + c] +
                             W1e2[k * 3 + 2] * Wl2[6 + c]);
        }
        if (t < 3)
            c2[t] = b1e2[0] * Wl2[0 + t] + b1e2[1] * Wl2[3 + t] +
                    b1e2[2] * Wl2[6 + t] + bl2[t];
    }
}
// Wcc = 0.5 * Wc @ WlB ; wa3/wg3 = Wl rows 128/129 @ WlB ; cc = c0 @ WlB + c2
__global__ void fuseC_kernel(const float* __restrict__ Wc, const float* __restrict__ c0,
                             const float* __restrict__ Wl1, const float* __restrict__ Wl2,
                             const float* __restrict__ c2,
                             float* __restrict__ Wcc, float* __restrict__ wa3,
                             float* __restrict__ wg3, float* __restrict__ cc)
{
    int id = threadIdx.x;   // 384
    int k = id / 3, c = id % 3;
    float s = 0.f;
#pragma unroll 8
    for (int j = 0; j < 128; j++) s += Wc[k * 128 + j] * Wl2[(3 + j) * 3 + c];
    Wcc[id] = 0.5f * s;
    if (id < 3) {
        float sa = 0.f, sg = 0.f, sc = 0.f;
        for (int j = 0; j < 128; j++) {
            float wb = Wl2[(3 + j) * 3 + id];
            sa += Wl1[128 * 128 + j] * wb;
            sg += Wl1[129 * 128 + j] * wb;
            sc += c0[j] * wb;
        }
        wa3[id] = sa; wg3[id] = sg; cc[id] = sc + c2[id];
    }
}

// ------------------------------------------------------------------
// CSR build: count (dst degrees) -> scan -> fill
__global__ void count_kernel(const int* __restrict__ ei, int* __restrict__ cnt)
{
    int e = blockIdx.x * blockDim.x + threadIdx.x;
    if (e < NE) atomicAdd(&cnt[ei[NE + e]], 1);
}

__global__ void __launch_bounds__(1024) scan_kernel(const int* __restrict__ cnt,
                                                    int* __restrict__ offs)
{
    __shared__ int part[1024];
    const int t = threadIdx.x;
    const int CH = (NN + 1023) / 1024;   // 49
    const int base = t * CH;
    int s = 0;
    for (int j = 0; j < CH; j++) {
        int n = base + j;
        if (n < NN) s += cnt[n];
    }
    part[t] = s;
    __syncthreads();
    for (int off = 1; off < 1024; off <<= 1) {
        int v = (t >= off) ? part[t - off] : 0;
        __syncthreads();
        part[t] += v;
        __syncthreads();
    }
    int run = part[t] - s;
    for (int j = 0; j < CH; j++) {
        int n = base + j;
        if (n < NN) { offs[n] = run; run += cnt[n]; }
    }
    if (t == 1023) offs[NN] = part[1023];
}

__global__ void fill_kernel(const int* __restrict__ ei, const int* __restrict__ offs,
                            int* __restrict__ cur, int* __restrict__ srcs)
{
    int e = blockIdx.x * blockDim.x + threadIdx.x;
    if (e < NE) {
        int src = ei[e];
        int dst = ei[NE + e];
        int pos = atomicAdd(&cur[dst], 1);
        srcs[offs[dst] + pos] = src;
    }
}

// ------------------------------------------------------------------
// node_proj: P[n][0..127] = x[n] @ W0[0:64,:] ; P[n][128..255] = x[n] @ W0[64:128,:]
__global__ void __launch_bounds__(256) node_proj_kernel(
    const float* __restrict__ x, const float* __restrict__ W0, __half* __restrict__ Ph)
{
    __shared__ float XT[64 * 68];
    __shared__ float WC[16 * 256];
    const int tid = threadIdx.x;
    const int nbase = blockIdx.x * 64;
#pragma unroll
    for (int i = 0; i < 4; i++) {
        int lin = tid * 4 + i;
        int r = lin >> 4, q = lin & 15;
        int node = nbase + r; if (node >= NN) node = NN - 1;
        float4 v = __ldg((const float4*)x + (size_t)node * 16 + q);
        XT[(q * 4 + 0) * 68 + r] = v.x;
        XT[(q * 4 + 1) * 68 + r] = v.y;
        XT[(q * 4 + 2) * 68 + r] = v.z;
        XT[(q * 4 + 3) * 68 + r] = v.w;
    }
    unsigned long long acc2[8][4];
#pragma unroll
    for (int i = 0; i < 8; i++)
#pragma unroll
        for (int j = 0; j < 4; j++) acc2[i][j] = 0ull;
    const int tr = tid >> 5, tc = tid & 31;
    for (int kc = 0; kc < 64; kc += 16) {
        __syncthreads();
#pragma unroll
        for (int i = 0; i < 4; i++) {
            int lin = tid + i * 256;
            int kk = lin >> 6, j4 = lin & 63;
            int j = j4 * 4;
            const float* src = (j < 128) ? (W0 + (kc + kk) * 128 + j)
                                         : (W0 + (64 + kc + kk) * 128 + (j - 128));
            *(float4*)&WC[kk * 256 + j] = *(const float4*)src;
        }
        __syncthreads();
#pragma unroll
        for (int kk = 0; kk < 16; kk++) {
            float4 a0 = *(const float4*)&XT[(kc + kk) * 68 + tr * 8];
            float4 a1 = *(const float4*)&XT[(kc + kk) * 68 + tr * 8 + 4];
            ulonglong2 w01 = *(const ulonglong2*)&WC[kk * 256 + tc * 8];
            ulonglong2 w23 = *(const ulonglong2*)&WC[kk * 256 + tc * 8 + 4];
            float a[8] = {a0.x, a0.y, a0.z, a0.w, a1.x, a1.y, a1.z, a1.w};
#pragma unroll
            for (int i = 0; i < 8; i++) {
                unsigned long long ap = pack2(a[i]);
                acc2[i][0] = ffma2(ap, w01.x, acc2[i][0]);
                acc2[i][1] = ffma2(ap, w01.y, acc2[i][1]);
                acc2[i][2] = ffma2(ap, w23.x, acc2[i][2]);
                acc2[i][3] = ffma2(ap, w23.y, acc2[i][3]);
            }
        }
    }
#pragma unroll
    for (int i = 0; i < 8; i++) {
        int node = nbase + tr * 8 + i;
        if (node < NN) {
            float o[8];
#pragma unroll
            for (int j = 0; j < 4; j++) unpack2(acc2[i][j], o[2 * j], o[2 * j + 1]);
            __half2 h0 = __floats2half2_rn(o[0], o[1]);
            __half2 h1 = __floats2half2_rn(o[2], o[3]);
            __half2 h2 = __floats2half2_rn(o[4], o[5]);
            __half2 h3 = __floats2half2_rn(o[6], o[7]);
            uint4 v;
            v.x = *(unsigned*)&h0; v.y = *(unsigned*)&h1;
            v.z = *(unsigned*)&h2; v.w = *(unsigned*)&h3;
            *(uint4*)&Ph[(size_t)node * 256 + tc * 8] = v;
        }
    }
}

// ------------------------------------------------------------------
// Fused CSR aggregation + per-node GEMM
__global__ void __launch_bounds__(256) aggregate_gemm_kernel(
    const __half* __restrict__ P, const int* __restrict__ offs,
    const int* __restrict__ srcs, const float* __restrict__ b0,
    const float* __restrict__ W1, const float* __restrict__ b1,
    float* __restrict__ x)
{
    __shared__ float W1S[128 * 64];
    __shared__ float HSH[8 * 128];
    __shared__ float B0S[128];
    __shared__ float B1S[64];
    const int tid = threadIdx.x;
    const int wid = tid >> 5, lane = tid & 31;

#pragma unroll
    for (int i = 0; i < 8; i++)
        ((float4*)W1S)[tid + i * 256] = ((const float4*)W1)[tid + i * 256];
    if (tid < 32) ((float4*)B0S)[tid] = ((const float4*)b0)[tid];
    else if (tid < 48) ((float4*)B1S)[tid - 32] = ((const float4*)b1)[tid - 32];
    __syncthreads();

    const int n = blockIdx.x * 8 + wid;
    if (n >= NN) return;

    const uint2* P4 = (const uint2*)P;
    float pbx, pby, pbz, pbw;
    h4_to_f4(__ldg(P4 + (size_t)n * 64 + 32 + lane), pbx, pby, pbz, pbw);
    float4 b0v = *(const float4*)&B0S[lane * 4];
    pbx += b0v.x; pby += b0v.y; pbz += b0v.z; pbw += b0v.w;

    const int beg = offs[n], end = offs[n + 1];
    float ax, ay, az, aw;
    float4 acc = make_float4(0.f, 0.f, 0.f, 0.f);
    int i = beg;
    for (; i + 4 <= end; i += 4) {
        int s0 = srcs[i], s1 = srcs[i + 1], s2 = srcs[i + 2], s3 = srcs[i + 3];
        uint2 u0 = __ldg(P4 + (size_t)s0 * 64 + lane);
        uint2 u1 = __ldg(P4 + (size_t)s1 * 64 + lane);
        uint2 u2 = __ldg(P4 + (size_t)s2 * 64 + lane);
        uint2 u3 = __ldg(P4 + (size_t)s3 * 64 + lane);
        h4_to_f4(u0, ax, ay, az, aw);
        acc.x += lrelu(ax + pbx); acc.y += lrelu(ay + pby);
        acc.z += lrelu(az + pbz); acc.w += lrelu(aw + pbw);
        h4_to_f4(u1, ax, ay, az, aw);
        acc.x += lrelu(ax + pbx); acc.y += lrelu(ay + pby);
        acc.z += lrelu(az + pbz); acc.w += lrelu(aw + pbw);
        h4_to_f4(u2, ax, ay, az, aw);
        acc.x += lrelu(ax + pbx); acc.y += lrelu(ay + pby);
        acc.z += lrelu(az + pbz); acc.w += lrelu(aw + pbw);
        h4_to_f4(u3, ax, ay, az, aw);
        acc.x += lrelu(ax + pbx); acc.y += lrelu(ay + pby);
        acc.z += lrelu(az + pbz); acc.w += lrelu(aw + pbw);
    }
    for (; i < end; i++) {
        int s = srcs[i];
        h4_to_f4(__ldg(P4 + (size_t)s * 64 + lane), ax, ay, az, aw);
        acc.x += lrelu(ax + pbx); acc.y += lrelu(ay + pby);
        acc.z += lrelu(az + pbz); acc.w += lrelu(aw + pbw);
    }
    *(float4*)&HSH[wid * 128 + lane * 4] = acc;
    __syncwarp();

    const float* h = &HSH[wid * 128];
    unsigned long long s2 = 0ull;
#pragma unroll 8
    for (int k = 0; k < 128; k++) {
        unsigned long long wv = *(const unsigned long long*)&W1S[k * 64 + lane * 2];
        s2 = ffma2(pack2(h[k]), wv, s2);
    }
    float s0f, s1f;
    unpack2(s2, s0f, s1f);
    int deg = end - beg;
    float inv = 1.f / fmaxf((float)deg, 1.f);
    float bf = deg > 0 ? 1.f : 0.f;
    float2 bv = *(const float2*)&B1S[lane * 2];
    *(float2*)&x[(size_t)n * 64 + lane * 2] =
        make_float2(s0f * inv + bv.x * bf, s1f * inv + bv.y * bf);
}

// ------------------------------------------------------------------
// merged edge kernel — fp16 W1/HD1, HMMA loss GEMM, 2 blocks/SM (grid 296)
#define EF_W1T  0        // half[128][136] transposed (W1T[n][k]) = 8704 floats
#define EF_HD1  8704     // half[64][132] = 4224 floats
#define EF_HS1  12928    // float[64][132] = 8448
#define EF_W12  21376    // 1568
#define EF_B0A  22944
#define EF_B0B  23072
#define EF_WA3  23200
#define EF_WG3  23208
#define EF_CCV  23216
#define EF_SPI  23232
#define EF_DPI  23296
#define EF_RED  23360
#define EF_TOT  23392
#define EF_GRID 296
#define EF_NTILE 12500
#define W12(k) ((k) * 12 + (((k) >> 5) << 2))

__global__ void __launch_bounds__(512) edge_fused_kernel(
    const __half* __restrict__ PB, const __half* __restrict__ PA2,
    const int* __restrict__ ei,
    const float* __restrict__ act, const float* __restrict__ ang,
    const float* __restrict__ b0B, const float* __restrict__ b0A,
    const float* __restrict__ W1,
    const float* __restrict__ Wc2, const float* __restrict__ W1e2,
    const float* __restrict__ Wcc,
    const float* __restrict__ wa3, const float* __restrict__ wg3,
    const float* __restrict__ ccv,
    float* __restrict__ out, double* __restrict__ lossp)
{
    extern __shared__ float sm[];
    __half* W1T = (__half*)(sm + EF_W1T);   // [n][k] stride 136
    __half* HD1h = (__half*)(sm + EF_HD1);  // [r][k] stride 132
    float* HS1 = sm + EF_HS1;               // [r][c] stride 132
    float* W12S = sm + EF_W12;
    float* B0A = sm + EF_B0A;
    float* B0B = sm + EF_B0B;
    float* WA3 = sm + EF_WA3;
    float* WG3 = sm + EF_WG3;
    float* CCV = sm + EF_CCV;
    int* SP = (int*)(sm + EF_SPI);
    int* DP = (int*)(sm + EF_DPI);
    float* RED = sm + EF_RED;
    const int tid = threadIdx.x;

    for (int i = tid; i < 16384; i += 512) {
        int k = i >> 7, n = i & 127;
        W1T[n * 136 + k] = __float2half_rn(W1[i]);
    }
    for (int i = tid; i < 1152; i += 512) {
        int k = i / 9, c = i % 9;
        float v = (c < 3) ? Wc2[k * 3 + c]
                : (c < 6) ? W1e2[k * 3 + (c - 3)]
                          : Wcc[k * 3 + (c - 6)];
        W12S[W12(k) + c] = v;
    }
    if (tid < 32) ((float4*)B0A)[tid] = ((const float4*)b0A)[tid];
    else if (tid < 64) ((float4*)B0B)[tid - 32] = ((const float4*)b0B)[tid - 32];
    if (tid < 3) { WA3[tid] = wa3[tid]; WG3[tid] = wg3[tid]; CCV[tid] = ccv[tid]; }

    const int w = tid >> 5, lane = tid & 31;
    const int group = w >> 3;                 // 0: matvec warps, 1: MMA warps
    const int wi = w & 7, gid = lane >> 2, tig = lane & 3;
    const int m0 = (wi & 3) * 16, n0 = (wi >> 2) * 64;
    const int p = (tid & 255) >> 2, q = tid & 3;
    float lsum = 0.f;

    for (int tile = blockIdx.x; tile < EF_NTILE; tile += EF_GRID) {
        const int pbase = tile * 64;
        __syncthreads();
        if (tid < 64) {
            SP[tid] = ei[pbase + tid];
            DP[tid] = ei[NP + pbase + tid];
        }
        __syncthreads();

#pragma unroll
        for (int it = 0; it < 4; it++) {
            int idx = tid + it * 512;
            int r = idx >> 5, c4 = idx & 31;
            int s = SP[r], d = DP[r];
            const uint2* Ps = (const uint2*)(PB + (size_t)s * 256);
            const uint2* Pd = (const uint2*)(PB + (size_t)d * 256);
            float a1x, a1y, a1z, a1w, b1x, b1y, b1z, b1w;
            float a2x, a2y, a2z, a2w, b2x, b2y, b2z, b2w;
            h4_to_f4(__ldg(Ps + c4),      a1x, a1y, a1z, a1w);
            h4_to_f4(__ldg(Pd + 32 + c4), b1x, b1y, b1z, b1w);
            h4_to_f4(__ldg(Pd + c4),      a2x, a2y, a2z, a2w);
            h4_to_f4(__ldg(Ps + 32 + c4), b2x, b2y, b2z, b2w);
            float4 b0v = *(const float4*)&B0B[c4 * 4];
            float h1, h2;
            float4 hs;
            float hdx, hdy, hdz, hdw;
            h1 = lrelu(a1x + b1x + b0v.x); h2 = lrelu(a2x + b2x + b0v.x);
            hs.x = h1 + h2; hdx = h1 - h2;
            h1 = lrelu(a1y + b1y + b0v.y); h2 = lrelu(a2y + b2y + b0v.y);
            hs.y = h1 + h2; hdy = h1 - h2;
            h1 = lrelu(a1z + b1z + b0v.z); h2 = lrelu(a2z + b2z + b0v.z);
            hs.z = h1 + h2; hdz = h1 - h2;
            h1 = lrelu(a1w + b1w + b0v.w); h2 = lrelu(a2w + b2w + b0v.w);
            hs.w = h1 + h2; hdw = h1 - h2;
            *(float4*)&HS1[r * 132 + c4 * 4] = hs;
            __half2 dlo = __floats2half2_rn(hdx, hdy);
            __half2 dhi = __floats2half2_rn(hdz, hdw);
            uint2 du; du.x = *(unsigned*)&dlo; du.y = *(unsigned*)&dhi;
            *(uint2*)&HD1h[r * 132 + c4 * 4] = du;
        }
        __syncthreads();

        if (group == 1) {
            float c[8][4];
#pragma unroll
            for (int nt = 0; nt < 8; nt++)
#pragma unroll
                for (int j = 0; j < 4; j++) c[nt][j] = 0.f;
#pragma unroll 2
            for (int ks = 0; ks < 8; ks++) {
                int kb = ks * 16;
                unsigned a0 = *(const unsigned*)&HD1h[(m0 + gid) * 132 + kb + 2 * tig];
                unsigned a1 = *(const unsigned*)&HD1h[(m0 + 8 + gid) * 132 + kb + 2 * tig];
                unsigned a2 = *(const unsigned*)&HD1h[(m0 + gid) * 132 + kb + 8 + 2 * tig];
                unsigned a3 = *(const unsigned*)&HD1h[(m0 + 8 + gid) * 132 + kb + 8 + 2 * tig];
#pragma unroll
                for (int nt = 0; nt < 8; nt++) {
                    int n = n0 + nt * 8 + gid;
                    unsigned b0f = *(const unsigned*)&W1T[n * 136 + kb + 2 * tig];
                    unsigned b1f = *(const unsigned*)&W1T[n * 136 + kb + 8 + 2 * tig];
                    mma_f16(c[nt], a0, a1, a2, a3, b0f, b1f);
                }
            }
#pragma unroll
            for (int nt = 0; nt < 8; nt++)
#pragma unroll
                for (int j = 0; j < 4; j++) lsum += c[nt][j] * c[nt][j];
        } else {
            const int gp = pbase + p;
            const int s = SP[p], d = DP[p];
            const uint2* Ps = (const uint2*)(PA2 + (size_t)s * 256);
            const uint2* Pd = (const uint2*)(PA2 + (size_t)d * 256);
            float o0 = 0.f, o1 = 0.f, o2 = 0.f, t0 = 0.f, t1 = 0.f, t2 = 0.f;
#pragma unroll
            for (int c8 = 0; c8 < 8; c8++) {
                int c4 = q * 8 + c8;
                float av1[4], bv1[4], av2[4], bv2[4];
                h4_to_f4(__ldg(Ps + c4),      av1[0], av1[1], av1[2], av1[3]);
                h4_to_f4(__ldg(Pd + 32 + c4), bv1[0], bv1[1], bv1[2], bv1[3]);
                h4_to_f4(__ldg(Pd + c4),      av2[0], av2[1], av2[2], av2[3]);
                h4_to_f4(__ldg(Ps + 32 + c4), bv2[0], bv2[1], bv2[2], bv2[3]);
                float4 hv = *(const float4*)&HS1[p * 132 + c4 * 4];
                float4 b0v = *(const float4*)&B0A[c4 * 4];
                float hsv[4] = {hv.x, hv.y, hv.z, hv.w};
                float b0a[4] = {b0v.x, b0v.y, b0v.z, b0v.w};
#pragma unroll
                for (int j = 0; j < 4; j++) {
                    int k = c4 * 4 + j;
                    float h1 = lrelu(av1[j] + bv1[j] + b0a[j]);
                    float h2 = lrelu(av2[j] + bv2[j] + b0a[j]);
                    float hs = h1 + h2, hd = h1 - h2, f = hsv[j];
                    const float* wv = &W12S[W12(k)];
                    o0 += hs * wv[0] + f * wv[6];
                    o1 += hs * wv[1] + f * wv[7];
                    o2 += hs * wv[2] + f * wv[8];
                    t0 += hd * wv[3];
                    t1 += hd * wv[4];
                    t2 += hd * wv[5];
                }
            }
#pragma unroll
            for (int off = 2; off > 0; off >>= 1) {
                o0 += __shfl_down_sync(0xffffffffu, o0, off, 4);
                o1 += __shfl_down_sync(0xffffffffu, o1, off, 4);
                o2 += __shfl_down_sync(0xffffffffu, o2, off, 4);
                t0 += __shfl_down_sync(0xffffffffu, t0, off, 4);
                t1 += __shfl_down_sync(0xffffffffu, t1, off, 4);
                t2 += __shfl_down_sync(0xffffffffu, t2, off, 4);
            }
            if (q == 0) {
                float av = __ldg(act + gp), gv = __ldg(ang + gp);
                out[(size_t)gp * 3 + 0] = o0 + av * WA3[0] + gv * WG3[0] + CCV[0];
                out[(size_t)gp * 3 + 1] = o1 + av * WA3[1] + gv * WG3[1] + CCV[1];
                out[(size_t)gp * 3 + 2] = o2 + av * WA3[2] + gv * WG3[2] + CCV[2];
                lsum += t0 * t0 + t1 * t1 + t2 * t2;
            }
        }
    }

#pragma unroll
    for (int o = 16; o > 0; o >>= 1) lsum += __shfl_down_sync(0xffffffffu, lsum, o);
    __syncthreads();
    if (lane == 0) RED[w] = lsum;
    __syncthreads();
    if (tid == 0) {
        float l2 = 0.f, l1 = 0.f;
#pragma unroll
        for (int ww = 0; ww < 8; ww++)  l2 += RED[ww];
#pragma unroll
        for (int ww = 8; ww < 16; ww++) l1 += RED[ww];
        atomicAdd(&lossp[0], (double)l1);
        atomicAdd(&lossp[1], (double)l2);
    }
}

// ------------------------------------------------------------------
__global__ void finalize_kernel(float* __restrict__ out, int idx)
{
    double l = 0.5 * (g_loss[0] / (800000.0 * 128.0) + g_loss[1] / (800000.0 * 3.0));
    out[idx] = (float)l;
}

// ------------------------------------------------------------------
extern "C" void kernel_launch(void* const* d_in, const int* in_sizes, int n_in,
                              void* d_out, int out_size)
{
    (void)in_sizes; (void)n_in;
    const float* xnf  = (const float*)d_in[0];
    const int*   ei   = (const int*)d_in[1];
    const float* ang  = (const float*)d_in[2];
    const float* act  = (const float*)d_in[3];
    const float* nc1W0 = (const float*)d_in[5];
    const float* nc1b0 = (const float*)d_in[6];
    const float* nc1W1 = (const float*)d_in[7];
    const float* nc1b1 = (const float*)d_in[8];
    const float* ec1W0 = (const float*)d_in[9];
    const float* ec1b0 = (const float*)d_in[10];
    const float* ec1W1 = (const float*)d_in[11];
    const float* ec1b1 = (const float*)d_in[12];
    const float* ec1Wl = (const float*)d_in[13];
    const float* ec1bl = (const float*)d_in[14];
    const float* nc2W0 = (const float*)d_in[15];
    const float* nc2b0 = (const float*)d_in[16];
    const float* nc2W1 = (const float*)d_in[17];
    const float* nc2b1 = (const float*)d_in[18];
    const float* ec2W0 = (const float*)d_in[19];
    const float* ec2b0 = (const float*)d_in[20];
    const float* ec2W1 = (const float*)d_in[21];
    const float* ec2b1 = (const float*)d_in[22];
    const float* ec2Wl = (const float*)d_in[23];
    const float* ec2bl = (const float*)d_in[24];
    float* out = (float*)d_out;

    float *x1, *x2, *Wc, *c0, *Wc2, *c2, *Wcc, *wa3, *wg3, *cc;
    __half *PA, *PB;
    int *cnt, *offs, *cur, *srcs;
    double* loss;
    cudaGetSymbolAddress((void**)&x1,   g_x1);
    cudaGetSymbolAddress((void**)&x2,   g_x2);
    cudaGetSymbolAddress((void**)&PA,   g_PA);
    cudaGetSymbolAddress((void**)&PB,   g_PB);
    cudaGetSymbolAddress((void**)&Wc,   g_Wc);
    cudaGetSymbolAddress((void**)&c0,   g_c0);
    cudaGetSymbolAddress((void**)&Wc2,  g_Wc2);
    cudaGetSymbolAddress((void**)&c2,   g_c2);
    cudaGetSymbolAddress((void**)&Wcc,  g_Wcc);
    cudaGetSymbolAddress((void**)&wa3,  g_wa3);
    cudaGetSymbolAddress((void**)&wg3,  g_wg3);
    cudaGetSymbolAddress((void**)&cc,   g_cc);
    cudaGetSymbolAddress((void**)&cnt,  g_cnt);
    cudaGetSymbolAddress((void**)&offs, g_offs);
    cudaGetSymbolAddress((void**)&cur,  g_cur);
    cudaGetSymbolAddress((void**)&srcs, g_srcs);
    cudaGetSymbolAddress((void**)&loss, g_loss);

    // One-time init OUTSIDE graph capture: smem attribute + streams/events.
    static int init_done = 0;
    static cudaStream_t s1, s2;
    static cudaEvent_t evFork, evCSR, evFuse, evX1, evPB;
    if (!init_done) {
        cudaFuncSetAttribute(edge_fused_kernel,
                             cudaFuncAttributeMaxDynamicSharedMemorySize,
                             EF_TOT * sizeof(float));
        cudaStreamCreateWithFlags(&s1, cudaStreamNonBlocking);
        cudaStreamCreateWithFlags(&s2, cudaStreamNonBlocking);
        cudaEventCreateWithFlags(&evFork, cudaEventDisableTiming);
        cudaEventCreateWithFlags(&evCSR,  cudaEventDisableTiming);
        cudaEventCreateWithFlags(&evFuse, cudaEventDisableTiming);
        cudaEventCreateWithFlags(&evX1,   cudaEventDisableTiming);
        cudaEventCreateWithFlags(&evPB,   cudaEventDisableTiming);
        init_done = 1;
    }

    const int NB64 = (NN + 63) / 64;
    const int NAGG = (NN + 7) / 8;
    const cudaStream_t s0 = 0;   // legacy/captured stream

    // fork side streams off the main stream
    cudaEventRecord(evFork, s0);
    cudaStreamWaitEvent(s1, evFork, 0);
    cudaStreamWaitEvent(s2, evFork, 0);

    // ---- s1: CSR build ----
    cudaMemsetAsync(cnt, 0, (size_t)NN * sizeof(int), s1);
    cudaMemsetAsync(cur, 0, (size_t)NN * sizeof(int), s1);
    count_kernel<<<(NE + 255) / 256, 256, 0, s1>>>(ei, cnt);
    scan_kernel<<<1, 1024, 0, s1>>>(cnt, offs);
    fill_kernel<<<(NE + 255) / 256, 256, 0, s1>>>(ei, offs, cur, srcs);
    cudaEventRecord(evCSR, s1);

    // ---- s2: weight fusions ----
    fuseAB_kernel<<<44, 384, 0, s2>>>(ec1W1, ec1Wl, ec1b1, ec1bl,
                                      ec2W1, ec2Wl, ec2b1, ec2bl,
                                      Wc, c0, Wc2, c2);
    fuseC_kernel<<<1, 384, 0, s2>>>(Wc, c0, ec1Wl, ec2Wl, c2, Wcc, wa3, wg3, cc);
    cudaEventRecord(evFuse, s2);

    // ---- s0: critical path ----
    cudaMemsetAsync(loss, 0, 2 * sizeof(double), s0);
    node_proj_kernel<<<NB64, 256, 0, s0>>>(xnf, nc1W0, PA);
    cudaStreamWaitEvent(s0, evCSR, 0);
    aggregate_gemm_kernel<<<NAGG, 256, 0, s0>>>(PA, offs, srcs, nc1b0, nc1W1, nc1b1, x1);
    cudaEventRecord(evX1, s0);

    // side: projection for edge conv 1 (needs x1 only)
    cudaStreamWaitEvent(s1, evX1, 0);
    node_proj_kernel<<<NB64, 256, 0, s1>>>(x1, ec1W0, PB);
    cudaEventRecord(evPB, s1);

    // main: conv layer 2 chain
    node_proj_kernel<<<NB64, 256, 0, s0>>>(x1, nc2W0, PA);
    aggregate_gemm_kernel<<<NAGG, 256, 0, s0>>>(PA, offs, srcs, nc2b0, nc2W1, nc2b1, x2);
    node_proj_kernel<<<NB64, 256, 0, s0>>>(x2, ec2W0, PA);

    // join and run merged edge convs
    cudaStreamWaitEvent(s0, evPB, 0);
    cudaStreamWaitEvent(s0, evFuse, 0);
    edge_fused_kernel<<<EF_GRID, 512, EF_TOT * sizeof(float), s0>>>(
        PB, PA, ei, act, ang, ec1b0, ec2b0, ec1W1,
        Wc2, ec2W1, Wcc, wa3, wg3, cc, out, loss);

    finalize_kernel<<<1, 1, 0, s0>>>(out, out_size - 1);
}

// round 13
// speedup vs baseline: 1.1535x; 1.0497x over previous
#include <cuda_runtime.h>
#include <cuda_fp16.h>

#define NN 50000
#define NP 800000   // undirected pairs
#define NE 1600000  // directed edges

// ---------------- scratch (static device globals; no allocations) ----------------
__device__ float  g_x1[NN * 64];
__device__ float  g_x2[NN * 64];
__device__ int    g_cnt[NN];
__device__ int    g_offs[NN + 1];
__device__ int    g_cur[NN];
__device__ int    g_srcs[NE];
__device__ __half g_PA[NN * 256];     // fp16 projection table A (conv1/conv2/ec2)
__device__ __half g_PB[NN * 256];     // fp16 projection table B (ec1)
__device__ float  g_Wc[16384];        // ec1: W1 @ Wl[0:128]
__device__ float  g_c0[128];          // ec1: b1 @ Wl[0:128] + bl
__device__ float  g_Wc2[384];         // ec2: 0.5 * W1e2 @ Wl2[0:3]
__device__ float  g_c2[4];            // ec2: b1e2 @ Wl2[0:3] + bl2
__device__ float  g_Wcc[384];         // 0.5 * Wc @ WlB   (fe1 folded into ec2)
__device__ float  g_wa3[4];           // wl128 @ WlB
__device__ float  g_wg3[4];           // wl129 @ WlB
__device__ float  g_cc[4];            // c0 @ WlB + c2
__device__ double g_loss[2];

__device__ __forceinline__ float lrelu(float z) { return z > 0.f ? z : 0.01f * z; }

// fp16 MMA m16n8k16
__device__ __forceinline__ void mma_f16(float c[4],
    unsigned a0, unsigned a1, unsigned a2, unsigned a3,
    unsigned b0, unsigned b1)
{
    asm volatile(
        "mma.sync.aligned.m16n8k16.row.col.f32.f16.f16.f32 "
        "{%0,%1,%2,%3}, {%4,%5,%6,%7}, {%8,%9}, {%0,%1,%2,%3};"
        : "+f"(c[0]), "+f"(c[1]), "+f"(c[2]), "+f"(c[3])
        : "r"(a0), "r"(a1), "r"(a2), "r"(a3), "r"(b0), "r"(b1));
}

// ---------------- packed f32x2 helpers ----------------
__device__ __forceinline__ unsigned long long pack2(float x)
{
    unsigned long long r;
    asm("mov.b64 %0, {%1, %1};" : "=l"(r) : "f"(x));
    return r;
}
__device__ __forceinline__ unsigned long long ffma2(
    unsigned long long a, unsigned long long b, unsigned long long c)
{
    unsigned long long d;
    asm("fma.rn.f32x2 %0, %1, %2, %3;" : "=l"(d) : "l"(a), "l"(b), "l"(c));
    return d;
}
__device__ __forceinline__ void unpack2(unsigned long long v, float& lo, float& hi)
{
    asm("mov.b64 {%0, %1}, %2;" : "=f"(lo), "=f"(hi) : "l"(v));
}

// half4 (uint2) -> 4 floats
__device__ __forceinline__ void h4_to_f4(uint2 u, float& f0, float& f1, float& f2, float& f3)
{
    __half2 p01 = *(__half2*)&u.x;
    __half2 p23 = *(__half2*)&u.y;
    float2 a = __half22float2(p01);
    float2 b = __half22float2(p23);
    f0 = a.x; f1 = a.y; f2 = b.x; f3 = b.y;
}

// ------------------------------------------------------------------
// Fused weight-precompute
__global__ void __launch_bounds__(384) fuseAB_kernel(
    const float* __restrict__ W1, const float* __restrict__ Wl,
    const float* __restrict__ b1, const float* __restrict__ bl,
    const float* __restrict__ W1e2, const float* __restrict__ Wl2,
    const float* __restrict__ b1e2, const float* __restrict__ bl2,
    float* __restrict__ Wc, float* __restrict__ c0,
    float* __restrict__ Wc2, float* __restrict__ c2)
{
    const int b = blockIdx.x, t = threadIdx.x;
    if (b < 43) {
        int id = b * 384 + t;
        if (id < 16384) {
            int r = id >> 7, c = id & 127;
            float s = 0.f;
#pragma unroll 8
            for (int k = 0; k < 128; k++) s += W1[r * 128 + k] * Wl[k * 128 + c];
            Wc[id] = s;
        }
    } else {
        if (t < 128) {
            float s = bl[t];
#pragma unroll 8
            for (int k = 0; k < 128; k++) s += b1[k] * Wl[k * 128 + t];
            c0[t] = s;
        }
        {
            int k = t / 3, c = t % 3;
            Wc2[t] = 0.5f * (W1e2[k * 3 + 0] * Wl2[0 + c] +
                             W1e2[k * 3 + 1] * Wl2[3 + c] +
                             W1e2[k * 3 + 2] * Wl2[6 + c]);
        }
        if (t < 3)
            c2[t] = b1e2[0] * Wl2[0 + t] + b1e2[1] * Wl2[3 + t] +
                    b1e2[2] * Wl2[6 + t] + bl2[t];
    }
}
__global__ void fuseC_kernel(const float* __restrict__ Wc, const float* __restrict__ c0,
                             const float* __restrict__ Wl1, const float* __restrict__ Wl2,
                             const float* __restrict__ c2,
                             float* __restrict__ Wcc, float* __restrict__ wa3,
                             float* __restrict__ wg3, float* __restrict__ cc)
{
    int id = threadIdx.x;   // 384
    int k = id / 3, c = id % 3;
    float s = 0.f;
#pragma unroll 8
    for (int j = 0; j < 128; j++) s += Wc[k * 128 + j] * Wl2[(3 + j) * 3 + c];
    Wcc[id] = 0.5f * s;
    if (id < 3) {
        float sa = 0.f, sg = 0.f, sc = 0.f;
        for (int j = 0; j < 128; j++) {
            float wb = Wl2[(3 + j) * 3 + id];
            sa += Wl1[128 * 128 + j] * wb;
            sg += Wl1[129 * 128 + j] * wb;
            sc += c0[j] * wb;
        }
        wa3[id] = sa; wg3[id] = sg; cc[id] = sc + c2[id];
    }
}

// ------------------------------------------------------------------
// CSR build
__global__ void count_kernel(const int* __restrict__ ei, int* __restrict__ cnt)
{
    int e = blockIdx.x * blockDim.x + threadIdx.x;
    if (e < NE) atomicAdd(&cnt[ei[NE + e]], 1);
}

__global__ void __launch_bounds__(1024) scan_kernel(const int* __restrict__ cnt,
                                                    int* __restrict__ offs)
{
    __shared__ int part[1024];
    const int t = threadIdx.x;
    const int CH = (NN + 1023) / 1024;   // 49
    const int base = t * CH;
    int s = 0;
    for (int j = 0; j < CH; j++) {
        int n = base + j;
        if (n < NN) s += cnt[n];
    }
    part[t] = s;
    __syncthreads();
    for (int off = 1; off < 1024; off <<= 1) {
        int v = (t >= off) ? part[t - off] : 0;
        __syncthreads();
        part[t] += v;
        __syncthreads();
    }
    int run = part[t] - s;
    for (int j = 0; j < CH; j++) {
        int n = base + j;
        if (n < NN) { offs[n] = run; run += cnt[n]; }
    }
    if (t == 1023) offs[NN] = part[1023];
}

__global__ void fill_kernel(const int* __restrict__ ei, const int* __restrict__ offs,
                            int* __restrict__ cur, int* __restrict__ srcs)
{
    int e = blockIdx.x * blockDim.x + threadIdx.x;
    if (e < NE) {
        int src = ei[e];
        int dst = ei[NE + e];
        int pos = atomicAdd(&cur[dst], 1);
        srcs[offs[dst] + pos] = src;
    }
}

// ------------------------------------------------------------------
// node_proj
__global__ void __launch_bounds__(256) node_proj_kernel(
    const float* __restrict__ x, const float* __restrict__ W0, __half* __restrict__ Ph)
{
    __shared__ float XT[64 * 68];
    __shared__ float WC[16 * 256];
    const int tid = threadIdx.x;
    const int nbase = blockIdx.x * 64;
#pragma unroll
    for (int i = 0; i < 4; i++) {
        int lin = tid * 4 + i;
        int r = lin >> 4, q = lin & 15;
        int node = nbase + r; if (node >= NN) node = NN - 1;
        float4 v = __ldg((const float4*)x + (size_t)node * 16 + q);
        XT[(q * 4 + 0) * 68 + r] = v.x;
        XT[(q * 4 + 1) * 68 + r] = v.y;
        XT[(q * 4 + 2) * 68 + r] = v.z;
        XT[(q * 4 + 3) * 68 + r] = v.w;
    }
    unsigned long long acc2[8][4];
#pragma unroll
    for (int i = 0; i < 8; i++)
#pragma unroll
        for (int j = 0; j < 4; j++) acc2[i][j] = 0ull;
    const int tr = tid >> 5, tc = tid & 31;
    for (int kc = 0; kc < 64; kc += 16) {
        __syncthreads();
#pragma unroll
        for (int i = 0; i < 4; i++) {
            int lin = tid + i * 256;
            int kk = lin >> 6, j4 = lin & 63;
            int j = j4 * 4;
            const float* src = (j < 128) ? (W0 + (kc + kk) * 128 + j)
                                         : (W0 + (64 + kc + kk) * 128 + (j - 128));
            *(float4*)&WC[kk * 256 + j] = *(const float4*)src;
        }
        __syncthreads();
#pragma unroll
        for (int kk = 0; kk < 16; kk++) {
            float4 a0 = *(const float4*)&XT[(kc + kk) * 68 + tr * 8];
            float4 a1 = *(const float4*)&XT[(kc + kk) * 68 + tr * 8 + 4];
            ulonglong2 w01 = *(const ulonglong2*)&WC[kk * 256 + tc * 8];
            ulonglong2 w23 = *(const ulonglong2*)&WC[kk * 256 + tc * 8 + 4];
            float a[8] = {a0.x, a0.y, a0.z, a0.w, a1.x, a1.y, a1.z, a1.w};
#pragma unroll
            for (int i = 0; i < 8; i++) {
                unsigned long long ap = pack2(a[i]);
                acc2[i][0] = ffma2(ap, w01.x, acc2[i][0]);
                acc2[i][1] = ffma2(ap, w01.y, acc2[i][1]);
                acc2[i][2] = ffma2(ap, w23.x, acc2[i][2]);
                acc2[i][3] = ffma2(ap, w23.y, acc2[i][3]);
            }
        }
    }
#pragma unroll
    for (int i = 0; i < 8; i++) {
        int node = nbase + tr * 8 + i;
        if (node < NN) {
            float o[8];
#pragma unroll
            for (int j = 0; j < 4; j++) unpack2(acc2[i][j], o[2 * j], o[2 * j + 1]);
            __half2 h0 = __floats2half2_rn(o[0], o[1]);
            __half2 h1 = __floats2half2_rn(o[2], o[3]);
            __half2 h2 = __floats2half2_rn(o[4], o[5]);
            __half2 h3 = __floats2half2_rn(o[6], o[7]);
            uint4 v;
            v.x = *(unsigned*)&h0; v.y = *(unsigned*)&h1;
            v.z = *(unsigned*)&h2; v.w = *(unsigned*)&h3;
            *(uint4*)&Ph[(size_t)node * 256 + tc * 8] = v;
        }
    }
}

// ------------------------------------------------------------------
// Fused CSR aggregation + per-node GEMM (prefetch depth 8)
__global__ void __launch_bounds__(256) aggregate_gemm_kernel(
    const __half* __restrict__ P, const int* __restrict__ offs,
    const int* __restrict__ srcs, const float* __restrict__ b0,
    const float* __restrict__ W1, const float* __restrict__ b1,
    float* __restrict__ x)
{
    __shared__ float W1S[128 * 64];
    __shared__ float HSH[8 * 128];
    __shared__ float B0S[128];
    __shared__ float B1S[64];
    const int tid = threadIdx.x;
    const int wid = tid >> 5, lane = tid & 31;

#pragma unroll
    for (int i = 0; i < 8; i++)
        ((float4*)W1S)[tid + i * 256] = ((const float4*)W1)[tid + i * 256];
    if (tid < 32) ((float4*)B0S)[tid] = ((const float4*)b0)[tid];
    else if (tid < 48) ((float4*)B1S)[tid - 32] = ((const float4*)b1)[tid - 32];
    __syncthreads();

    const int n = blockIdx.x * 8 + wid;
    if (n >= NN) return;

    const uint2* P4 = (const uint2*)P;
    float pbx, pby, pbz, pbw;
    h4_to_f4(__ldg(P4 + (size_t)n * 64 + 32 + lane), pbx, pby, pbz, pbw);
    float4 b0v = *(const float4*)&B0S[lane * 4];
    pbx += b0v.x; pby += b0v.y; pbz += b0v.z; pbw += b0v.w;

    const int beg = offs[n], end = offs[n + 1];
    float ax, ay, az, aw;
    float4 acc = make_float4(0.f, 0.f, 0.f, 0.f);
    int i = beg;
    for (; i + 8 <= end; i += 8) {
        uint2 u[8];
#pragma unroll
        for (int j = 0; j < 8; j++)
            u[j] = __ldg(P4 + (size_t)srcs[i + j] * 64 + lane);
#pragma unroll
        for (int j = 0; j < 8; j++) {
            h4_to_f4(u[j], ax, ay, az, aw);
            acc.x += lrelu(ax + pbx); acc.y += lrelu(ay + pby);
            acc.z += lrelu(az + pbz); acc.w += lrelu(aw + pbw);
        }
    }
    for (; i < end; i++) {
        int s = srcs[i];
        h4_to_f4(__ldg(P4 + (size_t)s * 64 + lane), ax, ay, az, aw);
        acc.x += lrelu(ax + pbx); acc.y += lrelu(ay + pby);
        acc.z += lrelu(az + pbz); acc.w += lrelu(aw + pbw);
    }
    *(float4*)&HSH[wid * 128 + lane * 4] = acc;
    __syncwarp();

    const float* h = &HSH[wid * 128];
    unsigned long long s2 = 0ull;
#pragma unroll 8
    for (int k = 0; k < 128; k++) {
        unsigned long long wv = *(const unsigned long long*)&W1S[k * 64 + lane * 2];
        s2 = ffma2(pack2(h[k]), wv, s2);
    }
    float s0f, s1f;
    unpack2(s2, s0f, s1f);
    int deg = end - beg;
    float inv = 1.f / fmaxf((float)deg, 1.f);
    float bf = deg > 0 ? 1.f : 0.f;
    float2 bv = *(const float2*)&B1S[lane * 2];
    *(float2*)&x[(size_t)n * 64 + lane * 2] =
        make_float2(s0f * inv + bv.x * bf, s1f * inv + bv.y * bf);
}

// ------------------------------------------------------------------
// merged edge kernel — sequential phases: all threads matvec (8/pair), then
// all 16 warps HMMA. 2 blocks/SM.
#define EF_W1T  0        // half[128][136] transposed (W1T[n][k]) = 8704 floats
#define EF_HD1  8704     // half[64][132] = 4224 floats
#define EF_HS1  12928    // float[64][132] = 8448
#define EF_W12  21376    // 1568
#define EF_B0A  22944
#define EF_B0B  23072
#define EF_WA3  23200
#define EF_WG3  23208
#define EF_CCV  23216
#define EF_SPI  23232
#define EF_DPI  23296
#define EF_RED  23360    // 32
#define EF_TOT  23392
#define EF_GRID 296
#define EF_NTILE 12500
#define W12(k) ((k) * 12 + (((k) >> 5) << 2))

__global__ void __launch_bounds__(512, 2) edge_fused_kernel(
    const __half* __restrict__ PB, const __half* __restrict__ PA2,
    const int* __restrict__ ei,
    const float* __restrict__ act, const float* __restrict__ ang,
    const float* __restrict__ b0B, const float* __restrict__ b0A,
    const float* __restrict__ W1,
    const float* __restrict__ Wc2, const float* __restrict__ W1e2,
    const float* __restrict__ Wcc,
    const float* __restrict__ wa3, const float* __restrict__ wg3,
    const float* __restrict__ ccv,
    float* __restrict__ out, double* __restrict__ lossp)
{
    extern __shared__ float sm[];
    __half* W1T = (__half*)(sm + EF_W1T);   // [n][k] stride 136
    __half* HD1h = (__half*)(sm + EF_HD1);  // [r][k] stride 132
    float* HS1 = sm + EF_HS1;               // [r][c] stride 132
    float* W12S = sm + EF_W12;
    float* B0A = sm + EF_B0A;
    float* B0B = sm + EF_B0B;
    float* WA3 = sm + EF_WA3;
    float* WG3 = sm + EF_WG3;
    float* CCV = sm + EF_CCV;
    int* SP = (int*)(sm + EF_SPI);
    int* DP = (int*)(sm + EF_DPI);
    float* RED = sm + EF_RED;
    const int tid = threadIdx.x;

    for (int i = tid; i < 16384; i += 512) {
        int k = i >> 7, n = i & 127;
        W1T[n * 136 + k] = __float2half_rn(W1[i]);
    }
    for (int i = tid; i < 1152; i += 512) {
        int k = i / 9, c = i % 9;
        float v = (c < 3) ? Wc2[k * 3 + c]
                : (c < 6) ? W1e2[k * 3 + (c - 3)]
                          : Wcc[k * 3 + (c - 6)];
        W12S[W12(k) + c] = v;
    }
    if (tid < 32) ((float4*)B0A)[tid] = ((const float4*)b0A)[tid];
    else if (tid < 64) ((float4*)B0B)[tid - 32] = ((const float4*)b0B)[tid - 32];
    if (tid < 3) { WA3[tid] = wa3[tid]; WG3[tid] = wg3[tid]; CCV[tid] = ccv[tid]; }

    const int w = tid >> 5, lane = tid & 31;
    const int gid = lane >> 2, tig = lane & 3;
    const int m0 = (w & 3) * 16, n0 = (w >> 2) * 32;   // 16 warps cover 64x128
    const int p = tid >> 3, q = tid & 7;               // 8 threads per pair
    float lsum1 = 0.f, lsum2 = 0.f;

    for (int tile = blockIdx.x; tile < EF_NTILE; tile += EF_GRID) {
        const int pbase = tile * 64;
        __syncthreads();
        if (tid < 64) {
            SP[tid] = ei[pbase + tid];
            DP[tid] = ei[NP + pbase + tid];
        }
        __syncthreads();

        // build HS1 (fp32) / HD1 (fp16) from fp16 PB
#pragma unroll
        for (int it = 0; it < 4; it++) {
            int idx = tid + it * 512;
            int r = idx >> 5, c4 = idx & 31;
            int s = SP[r], d = DP[r];
            const uint2* Ps = (const uint2*)(PB + (size_t)s * 256);
            const uint2* Pd = (const uint2*)(PB + (size_t)d * 256);
            float a1x, a1y, a1z, a1w, b1x, b1y, b1z, b1w;
            float a2x, a2y, a2z, a2w, b2x, b2y, b2z, b2w;
            h4_to_f4(__ldg(Ps + c4),      a1x, a1y, a1z, a1w);
            h4_to_f4(__ldg(Pd + 32 + c4), b1x, b1y, b1z, b1w);
            h4_to_f4(__ldg(Pd + c4),      a2x, a2y, a2z, a2w);
            h4_to_f4(__ldg(Ps + 32 + c4), b2x, b2y, b2z, b2w);
            float4 b0v = *(const float4*)&B0B[c4 * 4];
            float h1, h2;
            float4 hs;
            float hdx, hdy, hdz, hdw;
            h1 = lrelu(a1x + b1x + b0v.x); h2 = lrelu(a2x + b2x + b0v.x);
            hs.x = h1 + h2; hdx = h1 - h2;
            h1 = lrelu(a1y + b1y + b0v.y); h2 = lrelu(a2y + b2y + b0v.y);
            hs.y = h1 + h2; hdy = h1 - h2;
            h1 = lrelu(a1z + b1z + b0v.z); h2 = lrelu(a2z + b2z + b0v.z);
            hs.z = h1 + h2; hdz = h1 - h2;
            h1 = lrelu(a1w + b1w + b0v.w); h2 = lrelu(a2w + b2w + b0v.w);
            hs.w = h1 + h2; hdw = h1 - h2;
            *(float4*)&HS1[r * 132 + c4 * 4] = hs;
            __half2 dlo = __floats2half2_rn(hdx, hdy);
            __half2 dhi = __floats2half2_rn(hdz, hdw);
            uint2 du; du.x = *(unsigned*)&dlo; du.y = *(unsigned*)&dhi;
            *(uint2*)&HD1h[r * 132 + c4 * 4] = du;
        }
        __syncthreads();

        // ---- Phase A: per-pair matvec, 8 threads/pair (fp16 PA2 gathers) ----
        {
            const int gp = pbase + p;
            const int s = SP[p], d = DP[p];
            const uint2* Ps = (const uint2*)(PA2 + (size_t)s * 256);
            const uint2* Pd = (const uint2*)(PA2 + (size_t)d * 256);
            float o0 = 0.f, o1 = 0.f, o2 = 0.f, t0 = 0.f, t1 = 0.f, t2 = 0.f;
#pragma unroll
            for (int c8 = 0; c8 < 4; c8++) {
                int c4 = q * 4 + c8;
                float av1[4], bv1[4], av2[4], bv2[4];
                h4_to_f4(__ldg(Ps + c4),      av1[0], av1[1], av1[2], av1[3]);
                h4_to_f4(__ldg(Pd + 32 + c4), bv1[0], bv1[1], bv1[2], bv1[3]);
                h4_to_f4(__ldg(Pd + c4),      av2[0], av2[1], av2[2], av2[3]);
                h4_to_f4(__ldg(Ps + 32 + c4), bv2[0], bv2[1], bv2[2], bv2[3]);
                float4 hv = *(const float4*)&HS1[p * 132 + c4 * 4];
                float4 b0v = *(const float4*)&B0A[c4 * 4];
                float hsv[4] = {hv.x, hv.y, hv.z, hv.w};
                float b0a[4] = {b0v.x, b0v.y, b0v.z, b0v.w};
#pragma unroll
                for (int j = 0; j < 4; j++) {
                    int k = c4 * 4 + j;
                    float h1 = lrelu(av1[j] + bv1[j] + b0a[j]);
                    float h2 = lrelu(av2[j] + bv2[j] + b0a[j]);
                    float hsx = h1 + h2, hd = h1 - h2, f = hsv[j];
                    const float* wv = &W12S[W12(k)];
                    o0 += hsx * wv[0] + f * wv[6];
                    o1 += hsx * wv[1] + f * wv[7];
                    o2 += hsx * wv[2] + f * wv[8];
                    t0 += hd * wv[3];
                    t1 += hd * wv[4];
                    t2 += hd * wv[5];
                }
            }
#pragma unroll
            for (int off = 4; off > 0; off >>= 1) {
                o0 += __shfl_down_sync(0xffffffffu, o0, off, 8);
                o1 += __shfl_down_sync(0xffffffffu, o1, off, 8);
                o2 += __shfl_down_sync(0xffffffffu, o2, off, 8);
                t0 += __shfl_down_sync(0xffffffffu, t0, off, 8);
                t1 += __shfl_down_sync(0xffffffffu, t1, off, 8);
                t2 += __shfl_down_sync(0xffffffffu, t2, off, 8);
            }
            if (q == 0) {
                float av = __ldg(act + gp), gv = __ldg(ang + gp);
                out[(size_t)gp * 3 + 0] = o0 + av * WA3[0] + gv * WG3[0] + CCV[0];
                out[(size_t)gp * 3 + 1] = o1 + av * WA3[1] + gv * WG3[1] + CCV[1];
                out[(size_t)gp * 3 + 2] = o2 + av * WA3[2] + gv * WG3[2] + CCV[2];
                lsum2 += t0 * t0 + t1 * t1 + t2 * t2;
            }
        }

        // ---- Phase B: loss1 HMMA, all 16 warps (reads HD1h/W1T, synced above) ----
        {
            float c[4][4];
#pragma unroll
            for (int nt = 0; nt < 4; nt++)
#pragma unroll
                for (int j = 0; j < 4; j++) c[nt][j] = 0.f;
#pragma unroll 2
            for (int ks = 0; ks < 8; ks++) {
                int kb = ks * 16;
                unsigned a0 = *(const unsigned*)&HD1h[(m0 + gid) * 132 + kb + 2 * tig];
                unsigned a1 = *(const unsigned*)&HD1h[(m0 + 8 + gid) * 132 + kb + 2 * tig];
                unsigned a2 = *(const unsigned*)&HD1h[(m0 + gid) * 132 + kb + 8 + 2 * tig];
                unsigned a3 = *(const unsigned*)&HD1h[(m0 + 8 + gid) * 132 + kb + 8 + 2 * tig];
#pragma unroll
                for (int nt = 0; nt < 4; nt++) {
                    int n = n0 + nt * 8 + gid;
                    unsigned b0f = *(const unsigned*)&W1T[n * 136 + kb + 2 * tig];
                    unsigned b1f = *(const unsigned*)&W1T[n * 136 + kb + 8 + 2 * tig];
                    mma_f16(c[nt], a0, a1, a2, a3, b0f, b1f);
                }
            }
#pragma unroll
            for (int nt = 0; nt < 4; nt++)
#pragma unroll
                for (int j = 0; j < 4; j++) lsum1 += c[nt][j] * c[nt][j];
        }
    }

    // final loss reduce (both buckets per warp)
#pragma unroll
    for (int o = 16; o > 0; o >>= 1) {
        lsum1 += __shfl_down_sync(0xffffffffu, lsum1, o);
        lsum2 += __shfl_down_sync(0xffffffffu, lsum2, o);
    }
    __syncthreads();
    if (lane == 0) { RED[w] = lsum1; RED[16 + w] = lsum2; }
    __syncthreads();
    if (tid == 0) {
        float l1 = 0.f, l2 = 0.f;
#pragma unroll
        for (int ww = 0; ww < 16; ww++) { l1 += RED[ww]; l2 += RED[16 + ww]; }
        atomicAdd(&lossp[0], (double)l1);
        atomicAdd(&lossp[1], (double)l2);
    }
}

// ------------------------------------------------------------------
__global__ void finalize_kernel(float* __restrict__ out, int idx)
{
    double l = 0.5 * (g_loss[0] / (800000.0 * 128.0) + g_loss[1] / (800000.0 * 3.0));
    out[idx] = (float)l;
}

// ------------------------------------------------------------------
extern "C" void kernel_launch(void* const* d_in, const int* in_sizes, int n_in,
                              void* d_out, int out_size)
{
    (void)in_sizes; (void)n_in;
    const float* xnf  = (const float*)d_in[0];
    const int*   ei   = (const int*)d_in[1];
    const float* ang  = (const float*)d_in[2];
    const float* act  = (const float*)d_in[3];
    const float* nc1W0 = (const float*)d_in[5];
    const float* nc1b0 = (const float*)d_in[6];
    const float* nc1W1 = (const float*)d_in[7];
    const float* nc1b1 = (const float*)d_in[8];
    const float* ec1W0 = (const float*)d_in[9];
    const float* ec1b0 = (const float*)d_in[10];
    const float* ec1W1 = (const float*)d_in[11];
    const float* ec1b1 = (const float*)d_in[12];
    const float* ec1Wl = (const float*)d_in[13];
    const float* ec1bl = (const float*)d_in[14];
    const float* nc2W0 = (const float*)d_in[15];
    const float* nc2b0 = (const float*)d_in[16];
    const float* nc2W1 = (const float*)d_in[17];
    const float* nc2b1 = (const float*)d_in[18];
    const float* ec2W0 = (const float*)d_in[19];
    const float* ec2b0 = (const float*)d_in[20];
    const float* ec2W1 = (const float*)d_in[21];
    const float* ec2b1 = (const float*)d_in[22];
    const float* ec2Wl = (const float*)d_in[23];
    const float* ec2bl = (const float*)d_in[24];
    float* out = (float*)d_out;

    float *x1, *x2, *Wc, *c0, *Wc2, *c2, *Wcc, *wa3, *wg3, *cc;
    __half *PA, *PB;
    int *cnt, *offs, *cur, *srcs;
    double* loss;
    cudaGetSymbolAddress((void**)&x1,   g_x1);
    cudaGetSymbolAddress((void**)&x2,   g_x2);
    cudaGetSymbolAddress((void**)&PA,   g_PA);
    cudaGetSymbolAddress((void**)&PB,   g_PB);
    cudaGetSymbolAddress((void**)&Wc,   g_Wc);
    cudaGetSymbolAddress((void**)&c0,   g_c0);
    cudaGetSymbolAddress((void**)&Wc2,  g_Wc2);
    cudaGetSymbolAddress((void**)&c2,   g_c2);
    cudaGetSymbolAddress((void**)&Wcc,  g_Wcc);
    cudaGetSymbolAddress((void**)&wa3,  g_wa3);
    cudaGetSymbolAddress((void**)&wg3,  g_wg3);
    cudaGetSymbolAddress((void**)&cc,   g_cc);
    cudaGetSymbolAddress((void**)&cnt,  g_cnt);
    cudaGetSymbolAddress((void**)&offs, g_offs);
    cudaGetSymbolAddress((void**)&cur,  g_cur);
    cudaGetSymbolAddress((void**)&srcs, g_srcs);
    cudaGetSymbolAddress((void**)&loss, g_loss);

    // One-time init OUTSIDE graph capture.
    static int init_done = 0;
    static cudaStream_t s1, s2;
    static cudaEvent_t evFork, evCSR, evFuse, evX1, evPB;
    if (!init_done) {
        cudaFuncSetAttribute(edge_fused_kernel,
                             cudaFuncAttributeMaxDynamicSharedMemorySize,
                             EF_TOT * sizeof(float));
        cudaStreamCreateWithFlags(&s1, cudaStreamNonBlocking);
        cudaStreamCreateWithFlags(&s2, cudaStreamNonBlocking);
        cudaEventCreateWithFlags(&evFork, cudaEventDisableTiming);
        cudaEventCreateWithFlags(&evCSR,  cudaEventDisableTiming);
        cudaEventCreateWithFlags(&evFuse, cudaEventDisableTiming);
        cudaEventCreateWithFlags(&evX1,   cudaEventDisableTiming);
        cudaEventCreateWithFlags(&evPB,   cudaEventDisableTiming);
        init_done = 1;
    }

    const int NB64 = (NN + 63) / 64;
    const int NAGG = (NN + 7) / 8;
    const cudaStream_t s0 = 0;

    cudaEventRecord(evFork, s0);
    cudaStreamWaitEvent(s1, evFork, 0);
    cudaStreamWaitEvent(s2, evFork, 0);

    // ---- s1: CSR build ----
    cudaMemsetAsync(cnt, 0, (size_t)NN * sizeof(int), s1);
    cudaMemsetAsync(cur, 0, (size_t)NN * sizeof(int), s1);
    count_kernel<<<(NE + 255) / 256, 256, 0, s1>>>(ei, cnt);
    scan_kernel<<<1, 1024, 0, s1>>>(cnt, offs);
    fill_kernel<<<(NE + 255) / 256, 256, 0, s1>>>(ei, offs, cur, srcs);
    cudaEventRecord(evCSR, s1);

    // ---- s2: weight fusions ----
    fuseAB_kernel<<<44, 384, 0, s2>>>(ec1W1, ec1Wl, ec1b1, ec1bl,
                                      ec2W1, ec2Wl, ec2b1, ec2bl,
                                      Wc, c0, Wc2, c2);
    fuseC_kernel<<<1, 384, 0, s2>>>(Wc, c0, ec1Wl, ec2Wl, c2, Wcc, wa3, wg3, cc);
    cudaEventRecord(evFuse, s2);

    // ---- s0: critical path ----
    cudaMemsetAsync(loss, 0, 2 * sizeof(double), s0);
    node_proj_kernel<<<NB64, 256, 0, s0>>>(xnf, nc1W0, PA);
    cudaStreamWaitEvent(s0, evCSR, 0);
    aggregate_gemm_kernel<<<NAGG, 256, 0, s0>>>(PA, offs, srcs, nc1b0, nc1W1, nc1b1, x1);
    cudaEventRecord(evX1, s0);

    // side: projection for edge conv 1 (needs x1 only)
    cudaStreamWaitEvent(s1, evX1, 0);
    node_proj_kernel<<<NB64, 256, 0, s1>>>(x1, ec1W0, PB);
    cudaEventRecord(evPB, s1);

    // main: conv layer 2 chain
    node_proj_kernel<<<NB64, 256, 0, s0>>>(x1, nc2W0, PA);
    aggregate_gemm_kernel<<<NAGG, 256, 0, s0>>>(PA, offs, srcs, nc2b0, nc2W1, nc2b1, x2);
    node_proj_kernel<<<NB64, 256, 0, s0>>>(x2, ec2W0, PA);

    // join and run merged edge convs
    cudaStreamWaitEvent(s0, evPB, 0);
    cudaStreamWaitEvent(s0, evFuse, 0);
    edge_fused_kernel<<<EF_GRID, 512, EF_TOT * sizeof(float), s0>>>(
        PB, PA, ei, act, ang, ec1b0, ec2b0, ec1W1,
        Wc2, ec2W1, Wcc, wa3, wg3, cc, out, loss);

    finalize_kernel<<<1, 1, 0, s0>>>(out, out_size - 1);
}